// round 2
// baseline (speedup 1.0000x reference)
#include <cuda_runtime.h>
#include <math.h>

#define NN 1024
#define DIM 64
#define NH 64
#define NC 13
#define SCALE 0.125f
#define KMAX 20
#define NB 64
#define NT 256
#define RPB 16            // rows per block (NN/NB)
#define GATE_THR (-2.1972245773362196f)   // logit(0.1): sigmoid(l)>0.1 <=> l>THR

// -------- device scratch --------
__device__ float g_q[NH][NN], g_k[NH][NN], g_v[NH][NN];
__device__ float g_gq[NH][NN], g_gk[NH][NN], g_gv[NH][NN];
__device__ float g_xpart[NB][DIM];
__device__ float g_entpart[NH];
__device__ float g_lx[NN * DIM];
__device__ float g_gx[NN * DIM];
__device__ unsigned g_barcnt[4];   // zero-initialized at module load; monotonic

__constant__ float c_invf[14] = {
    1.0f, 1.0f, 0.5f, 1.66666672e-01f, 4.16666679e-02f, 8.33333377e-03f,
    1.38888892e-03f, 1.98412701e-04f, 2.48015876e-05f, 2.75573188e-06f,
    2.75573192e-07f, 2.50521084e-08f, 2.08767563e-09f, 1.60590438e-10f };

__device__ __forceinline__ unsigned ford(float f) {
    unsigned u = __float_as_uint(f);
    return (u & 0x80000000u) ? ~u : (u | 0x80000000u);
}

__device__ __forceinline__ float horner13s(const float* c, float a) {
    float r = c[12];
#pragma unroll
    for (int j = 11; j >= 0; --j) r = fmaf(r, a, c[j]);
    return r;
}

// grid-wide barrier, safe across graph replays (monotonic counter, never reset)
__device__ __forceinline__ void gridbar(int idx) {
    __syncthreads();
    if (threadIdx.x == 0) {
        __threadfence();
        unsigned my = atomicAdd(&g_barcnt[idx], 1u);
        unsigned target = (my / (unsigned)NB + 1u) * (unsigned)NB;
        while (*(volatile unsigned*)&g_barcnt[idx] < target) { __nanosleep(64); }
        __threadfence();
    }
    __syncthreads();
}

__global__ __launch_bounds__(NT, 1)
void fused_kernel(const float* __restrict__ x,
                  const float* __restrict__ qkv_w,  const float* __restrict__ qkv_b,
                  const float* __restrict__ gqkv_w, const float* __restrict__ gqkv_b,
                  const float* __restrict__ cg_w,   const float* __restrict__ cg_b,
                  const float* __restrict__ hg_w,   const float* __restrict__ hg_b,
                  const float* __restrict__ fus_w,  const float* __restrict__ fus_b,
                  const float* __restrict__ proj_w, const float* __restrict__ proj_b,
                  float* __restrict__ out) {
    // ---- shared memory ----
    __shared__ float xs[RPB * 64];     // original x rows (persists A->C)
    __shared__ float xmS[RPB * 64];    // masked x rows (persists A->C)
    __shared__ float qs[NN];           // phase B: q col   | phase C: lx
    __shared__ float kk[NN];           // phase B: k col   | phase C: gx
    __shared__ float vv[NN];           // phase B: v col   | phase C: tmp
    __shared__ float gqs[NN], gk[NN], gv[NN];
    __shared__ unsigned long long keys[NN];
    __shared__ float red[40][8];
    __shared__ float Rall[40];
    __shared__ float coefD[NC], coefS1[NC], coefDg[NC], coefSv[NC];
    __shared__ float tk[KMAX], tv[KMAX], bk[KMAX], bv[KMAX];
    __shared__ float cLp[NC], cLn[NC];
    __shared__ float sred[64];
    __shared__ int   km_s, early_s;

    const int b = blockIdx.x;
    const int t = threadIdx.x;
    const int lane = t & 31, wid = t >> 5;
    const int n0 = b * RPB;

    // ================= Phase A: gate + qkv/gqkv GEMMs (16 rows) =================
    for (int i = t; i < RPB * 64; i += NT) xs[i] = x[n0 * 64 + i];
    __syncthreads();

    if (t < 64) {  // per-column partial sum of x (for importance)
        float s = 0.f;
#pragma unroll
        for (int r = 0; r < RPB; ++r) s += xs[r * 64 + t];
        g_xpart[b][t] = s;
    }

    {   // content gate -> masked xm
        int c = t & 63, r0 = t >> 6;
        for (int r = r0; r < RPB; r += 4) {
            float l = cg_b[c];
#pragma unroll 8
            for (int j = 0; j < 64; ++j) l = fmaf(xs[r * 64 + j], cg_w[j * 64 + c], l);
            xmS[r * 64 + c] = (l > (float)GATE_THR) ? xs[r * 64 + c] : 0.f;
        }
    }
    __syncthreads();

    // qkv (192 cols) + gqkv (192 cols), 16-row register tile per column-thread
    for (int cc = t; cc < 384; cc += NT) {
        const bool isg = (cc >= 192);
        const int c = isg ? cc - 192 : cc;
        const float* wp = isg ? gqkv_w : qkv_w;
        float acc[RPB];
        float bias = isg ? gqkv_b[c] : qkv_b[c];
#pragma unroll
        for (int r = 0; r < RPB; ++r) acc[r] = bias;
        for (int j = 0; j < 64; ++j) {
            float w = wp[j * 192 + c];
#pragma unroll
            for (int r = 0; r < RPB; ++r) acc[r] = fmaf(xmS[r * 64 + j], w, acc[r]);
        }
        const int h = c & 63, part = c >> 6;   // 0=q 1=k 2=v
        float* dst = isg ? (part == 0 ? &g_gq[h][0] : part == 1 ? &g_gk[h][0] : &g_gv[h][0])
                         : (part == 0 ? &g_q[h][0]  : part == 1 ? &g_k[h][0]  : &g_v[h][0]);
        float4* d4 = (float4*)(dst + n0);
#pragma unroll
        for (int r = 0; r < RPB; r += 4)
            d4[r >> 2] = make_float4(acc[r], acc[r + 1], acc[r + 2], acc[r + 3]);
    }

    gridbar(0);

    // ================= Phase B: per-head (h = blockIdx) =================
    const int h = b;
    for (int i = t; i < NN; i += NT) {
        qs[i]  = g_q[h][i];  kk[i] = g_k[h][i];  vv[i] = g_v[h][i];
        gqs[i] = g_gq[h][i]; gk[i] = g_gk[h][i]; gv[i] = g_gv[h][i];
    }
    __syncthreads();

    // moments of k (0..13)
    {
        float M[14];
#pragma unroll
        for (int j = 0; j < 14; ++j) M[j] = 0.f;
        for (int m = t; m < NN; m += NT) {
            float kv = kk[m], p = 1.f;
#pragma unroll
            for (int j = 0; j < 14; ++j) { M[j] += p; p *= kv; }
        }
#pragma unroll
        for (int j = 0; j < 14; ++j) {
            float v = M[j];
            for (int o = 16; o; o >>= 1) v += __shfl_down_sync(0xffffffffu, v, o);
            if (lane == 0) red[j][wid] = v;
        }
    }
    // moments of gk and gv*gk (0..12)
    {
        float Mg[NC], Wg[NC];
#pragma unroll
        for (int j = 0; j < NC; ++j) { Mg[j] = 0.f; Wg[j] = 0.f; }
        for (int m = t; m < NN; m += NT) {
            float gkv = gk[m], gvv = gv[m], p = 1.f;
#pragma unroll
            for (int j = 0; j < NC; ++j) { Mg[j] += p; Wg[j] += gvv * p; p *= gkv; }
        }
#pragma unroll
        for (int j = 0; j < NC; ++j) {
            float v = Mg[j];
            for (int o = 16; o; o >>= 1) v += __shfl_down_sync(0xffffffffu, v, o);
            if (lane == 0) red[14 + j][wid] = v;
            float w = Wg[j];
            for (int o = 16; o; o >>= 1) w += __shfl_down_sync(0xffffffffu, w, o);
            if (lane == 0) red[27 + j][wid] = w;
        }
    }
    __syncthreads();
    if (t < 40) {
        float s = 0.f;
#pragma unroll
        for (int w = 0; w < 8; ++w) s += red[t][w];
        Rall[t] = s;
    }
    __syncthreads();
    if (t < NC) {
        float f = c_invf[t];
        coefD[t]  = Rall[t] * f;
        coefS1[t] = Rall[t + 1] * f;
        coefDg[t] = Rall[14 + t] * f;
        coefSv[t] = Rall[27 + t] * f;
    }

    // bitonic sort of (k, index) keys — one sort gives top-20 and bottom-20
    for (int m = t; m < NN; m += NT)
        keys[m] = ((unsigned long long)ford(kk[m]) << 32) | (unsigned)(1023 - m);
    __syncthreads();
    for (int ks = 2; ks <= NN; ks <<= 1) {
        for (int js = ks >> 1; js > 0; js >>= 1) {
            for (int i = t; i < NN; i += NT) {
                int ixj = i ^ js;
                if (ixj > i) {
                    bool up = ((i & ks) == 0);
                    unsigned long long a0 = keys[i], a1 = keys[ixj];
                    if ((a0 > a1) == up) { keys[i] = a1; keys[ixj] = a0; }
                }
            }
            __syncthreads();
        }
    }
    if (t < KMAX) {
        unsigned long long kt = keys[1023 - t];          // t-th largest k (tie: low idx)
        int m = 1023 - (int)(unsigned)kt;
        tk[t] = kk[m]; tv[t] = vv[m];
        unsigned long long kb = keys[t];                 // t-th smallest k
        m = 1023 - (int)(unsigned)kb;
        bk[t] = kk[m]; bv[t] = vv[m];
    }
    __syncthreads();

    // entropy + global attention output
    float ent = 0.f;
    for (int n = t; n < NN; n += NT) {
        float a = qs[n] * SCALE;
        float D = horner13s(coefD, a);
        float S1 = horner13s(coefS1, a);
        ent += __logf(D) - a * S1 / D;
        float ag = gqs[n] * SCALE;
        g_gx[n * 64 + h] = horner13s(coefSv, ag) / horner13s(coefDg, ag);
    }
    for (int o = 16; o; o >>= 1) ent += __shfl_down_sync(0xffffffffu, ent, o);
    if (lane == 0) red[0][wid] = ent;
    __syncthreads();
    if (t == 0) {
        float s = 0.f;
#pragma unroll
        for (int w = 0; w < 8; ++w) s += red[0][w];
        g_entpart[h] = s;
    }

    gridbar(1);

    // km (identical in every block, fixed-order sum -> deterministic)
    if (t == 0) {
        float s = 0.f;
        for (int hh = 0; hh < NH; ++hh) s += g_entpart[hh];
        float em = s * (1.f / (float)(NH * NN));
        int km = 5 + (int)rintf(15.f * em);
        if (km < 5) km = 5;
        if (km > 20) km = 20;
        km_s = km;
    }
    __syncthreads();
    const int km = km_s;

    // Taylor coefficients of the local numerator for both sign branches
    if (t < NC) {
        float sp = 0.f, sn = 0.f;
        for (int i = 0; i < km; ++i) {
            float pp = 1.f, pn = 1.f;
            for (int jj = 0; jj < t; ++jj) { pp *= tk[i]; pn *= bk[i]; }
            sp += tv[i] * pp;
            sn += bv[i] * pn;
        }
        cLp[t] = sp * c_invf[t];
        cLn[t] = sn * c_invf[t];
    }
    __syncthreads();

    // local attention output
    for (int n = t; n < NN; n += NT) {
        float a = qs[n] * SCALE;
        float D = horner13s(coefD, a);
        float num;
        if (a > 0.f)      num = horner13s(cLp, a);
        else if (a < 0.f) num = horner13s(cLn, a);
        else { num = 0.f; for (int m = 0; m < km; ++m) num += vv[m]; }
        g_lx[n * 64 + h] = num / D;
    }

    gridbar(2);

    // ================= Phase C: fuse + residual + proj (16 rows) =================
    float* lxS = qs;   // reuse
    float* gxS = kk;
    float* ttS = vv;
    for (int i = t; i < RPB * 64; i += NT) {
        lxS[i] = g_lx[n0 * 64 + i];
        gxS[i] = g_gx[n0 * 64 + i];
    }
    if (t < 64) {      // importance / early flag (identical per block)
        float cs = 0.f;
#pragma unroll
        for (int bb = 0; bb < NB; ++bb) cs += g_xpart[bb][t];
        sred[t] = cs * (1.f / (float)NN) * hg_w[t];
    }
    __syncthreads();
    if (t == 0) {
        float l = hg_b[0];
#pragma unroll
        for (int j = 0; j < 64; ++j) l += sred[j];
        float imp = 1.f / (1.f + expf(-l));
        early_s = (imp < 0.1f) ? 1 : 0;
    }

    const int c = t & 63, r0 = t >> 6;
    for (int r = r0; r < RPB; r += 4) {
        float f = fus_b[c];
#pragma unroll 8
        for (int j = 0; j < 64; ++j) f = fmaf(lxS[r * 64 + j], fus_w[j * 64 + c], f);
#pragma unroll 8
        for (int j = 0; j < 64; ++j) f = fmaf(gxS[r * 64 + j], fus_w[(64 + j) * 64 + c], f);
        ttS[r * 64 + c] = xmS[r * 64 + c] + f;
    }
    __syncthreads();
    const int early = early_s;
    for (int r = r0; r < RPB; r += 4) {
        float o = proj_b[c];
#pragma unroll 8
        for (int j = 0; j < 64; ++j) o = fmaf(ttS[r * 64 + j], proj_w[j * 64 + c], o);
        out[(n0 + r) * 64 + c] = early ? xs[r * 64 + c] : o;
    }
}

extern "C" void kernel_launch(void* const* d_in, const int* in_sizes, int n_in,
                              void* d_out, int out_size) {
    const float* x      = (const float*)d_in[0];
    const float* qkv_w  = (const float*)d_in[1];
    const float* qkv_b  = (const float*)d_in[2];
    const float* gqkv_w = (const float*)d_in[3];
    const float* gqkv_b = (const float*)d_in[4];
    const float* cg_w   = (const float*)d_in[5];
    const float* cg_b   = (const float*)d_in[6];
    const float* hg_w   = (const float*)d_in[7];
    const float* hg_b   = (const float*)d_in[8];
    const float* fus_w  = (const float*)d_in[9];
    const float* fus_b  = (const float*)d_in[10];
    const float* proj_w = (const float*)d_in[11];
    const float* proj_b = (const float*)d_in[12];
    float* out = (float*)d_out;

    fused_kernel<<<NB, NT>>>(x, qkv_w, qkv_b, gqkv_w, gqkv_b, cg_w, cg_b,
                             hg_w, hg_b, fus_w, fus_b, proj_w, proj_b, out);
}

// round 3
// speedup vs baseline: 1.3212x; 1.3212x over previous
#include <cuda_runtime.h>
#include <math.h>

#define NN 1024
#define NH 64
#define NC 13
#define SCALE 0.125f
#define KMAX 20
#define NB 128
#define NT 256
#define RPB 8             // rows per block (NN/NB)
#define GATE_THR (-2.1972245773362196f)   // logit(0.1)

// -------- device scratch --------
__device__ float g_q[NH][NN], g_k[NH][NN], g_v[NH][NN];
__device__ float g_gq[NH][NN], g_gk[NH][NN], g_gv[NH][NN];
__device__ float g_xpart[NB][64];
__device__ float g_entpart[NB];
__device__ float g_lx[NN * 64];
__device__ float g_gx[NN * 64];
__device__ unsigned g_barcnt[4];   // zero-init; monotonic across graph replays

__constant__ float c_invf[14] = {
    1.0f, 1.0f, 0.5f, 1.66666672e-01f, 4.16666679e-02f, 8.33333377e-03f,
    1.38888892e-03f, 1.98412701e-04f, 2.48015876e-05f, 2.75573188e-06f,
    2.75573192e-07f, 2.50521084e-08f, 2.08767563e-09f, 1.60590438e-10f };

__device__ __forceinline__ unsigned ford(float f) {
    unsigned u = __float_as_uint(f);
    return (u & 0x80000000u) ? ~u : (u | 0x80000000u);
}

__device__ __forceinline__ float horner13s(const float* c, float a) {
    float r = c[12];
#pragma unroll
    for (int j = 11; j >= 0; --j) r = fmaf(r, a, c[j]);
    return r;
}

__device__ __forceinline__ void gridbar(int idx) {
    __syncthreads();
    if (threadIdx.x == 0) {
        __threadfence();
        unsigned my = atomicAdd(&g_barcnt[idx], 1u);
        unsigned target = (my / (unsigned)NB + 1u) * (unsigned)NB;
        while (*(volatile unsigned*)&g_barcnt[idx] < target) { __nanosleep(32); }
        __threadfence();
    }
    __syncthreads();
}

__global__ __launch_bounds__(NT, 1)
void fused_kernel(const float* __restrict__ x,
                  const float* __restrict__ qkv_w,  const float* __restrict__ qkv_b,
                  const float* __restrict__ gqkv_w, const float* __restrict__ gqkv_b,
                  const float* __restrict__ cg_w,   const float* __restrict__ cg_b,
                  const float* __restrict__ hg_w,   const float* __restrict__ hg_b,
                  const float* __restrict__ fus_w,  const float* __restrict__ fus_b,
                  const float* __restrict__ proj_w, const float* __restrict__ proj_b,
                  float* __restrict__ out) {
    __shared__ float xs[RPB * 64];     // original x rows (persists A->C)
    __shared__ float xmS[RPB * 64];    // masked x rows (persists A->C)
    __shared__ float qs[512], gqs[512];
    __shared__ float kk[NN], vv[NN], gk[NN], gv[NN];
    __shared__ unsigned long long candT[80], candB[80];
    __shared__ float red[40][8];
    __shared__ float Rall[40];
    __shared__ float coefD[NC], coefS1[NC], coefDg[NC], coefSv[NC];
    __shared__ float tk[KMAX], tv[KMAX], bk[KMAX], bv[KMAX];
    __shared__ float cLp[NC], cLn[NC];
    __shared__ float sred[64];
    __shared__ int   km_s, early_s;

    const int b = blockIdx.x;
    const int t = threadIdx.x;
    const int lane = t & 31, wid = t >> 5;
    const int n0 = b * RPB;

    // ================= Phase A: gate + qkv/gqkv GEMMs (8 rows) =================
    for (int i = t; i < RPB * 64; i += NT) xs[i] = x[n0 * 64 + i];
    __syncthreads();

    if (t < 64) {
        float s = 0.f;
#pragma unroll
        for (int r = 0; r < RPB; ++r) s += xs[r * 64 + t];
        g_xpart[b][t] = s;
    }

    {   // content gate: 512 outputs, 2 per thread
        const int c = t & 63;
#pragma unroll
        for (int rr = 0; rr < 2; ++rr) {
            const int r = (t >> 6) + rr * 4;
            float l = cg_b[c];
#pragma unroll 8
            for (int j = 0; j < 64; ++j) l = fmaf(xs[r * 64 + j], cg_w[j * 64 + c], l);
            xmS[r * 64 + c] = (l > (float)GATE_THR) ? xs[r * 64 + c] : 0.f;
        }
    }
    __syncthreads();

    // qkv (192 cols) + gqkv (192 cols): 8-row register tile per column-thread
    for (int cc = t; cc < 384; cc += NT) {
        const bool isg = (cc >= 192);
        const int c = isg ? cc - 192 : cc;
        const float* wp = isg ? gqkv_w : qkv_w;
        float acc[RPB];
        const float bias = isg ? gqkv_b[c] : qkv_b[c];
#pragma unroll
        for (int r = 0; r < RPB; ++r) acc[r] = bias;
#pragma unroll 8
        for (int j = 0; j < 64; ++j) {
            const float w = wp[j * 192 + c];
#pragma unroll
            for (int r = 0; r < RPB; ++r) acc[r] = fmaf(xmS[r * 64 + j], w, acc[r]);
        }
        const int h = c & 63, part = c >> 6;
        float* dst = isg ? (part == 0 ? g_gq[h] : part == 1 ? g_gk[h] : g_gv[h])
                         : (part == 0 ? g_q[h]  : part == 1 ? g_k[h]  : g_v[h]);
        float4* d4 = (float4*)(dst + n0);
#pragma unroll
        for (int r = 0; r < RPB; r += 4)
            d4[r >> 2] = make_float4(acc[r], acc[r + 1], acc[r + 2], acc[r + 3]);
    }

    gridbar(0);

    // ================= Phase B: head h, half of rows =================
    const int h = b >> 1, half = b & 1;
#pragma unroll
    for (int ii = 0; ii < 4; ++ii) {
        const int i = t + ii * NT;
        kk[i] = g_k[h][i];  vv[i] = g_v[h][i];
        gk[i] = g_gk[h][i]; gv[i] = g_gv[h][i];
    }
#pragma unroll
    for (int ii = 0; ii < 2; ++ii) {
        const int i = t + ii * NT;
        qs[i]  = g_q[h][half * 512 + i];
        gqs[i] = g_gq[h][half * 512 + i];
    }
    __syncthreads();

    // ---- moments ----
    {
        float M[14], Mg[NC], Wg[NC];
#pragma unroll
        for (int j = 0; j < 14; ++j) M[j] = 0.f;
#pragma unroll
        for (int j = 0; j < NC; ++j) { Mg[j] = 0.f; Wg[j] = 0.f; }
#pragma unroll
        for (int ii = 0; ii < 4; ++ii) {
            const int m = t + ii * NT;
            const float kv = kk[m];
            float p = 1.f;
#pragma unroll
            for (int j = 0; j < 14; ++j) { M[j] += p; p *= kv; }
            const float gkv = gk[m], gvv = gv[m];
            float pg = 1.f;
#pragma unroll
            for (int j = 0; j < NC; ++j) { Mg[j] += pg; Wg[j] += gvv * pg; pg *= gkv; }
        }
#pragma unroll
        for (int j = 0; j < 14; ++j) {
            float v = M[j];
            for (int o = 16; o; o >>= 1) v += __shfl_down_sync(0xffffffffu, v, o);
            if (lane == 0) red[j][wid] = v;
        }
#pragma unroll
        for (int j = 0; j < NC; ++j) {
            float v = Mg[j];
            for (int o = 16; o; o >>= 1) v += __shfl_down_sync(0xffffffffu, v, o);
            if (lane == 0) red[14 + j][wid] = v;
            float w = Wg[j];
            for (int o = 16; o; o >>= 1) w += __shfl_down_sync(0xffffffffu, w, o);
            if (lane == 0) red[27 + j][wid] = w;
        }
    }

    // ---- warp-select: warps 0-3 top-20, warps 4-7 bottom-20 (no barriers) ----
    {
        const int sw = wid & 3;
        const bool isBot = (wid >= 4);
        unsigned long long key[8];
#pragma unroll
        for (int i = 0; i < 8; ++i) {
            const int m = sw * 256 + i * 32 + lane;
            unsigned f = ford(kk[m]);
            if (isBot) f = ~f;
            key[i] = ((unsigned long long)f << 32) | (unsigned)(1023 - m);
        }
        unsigned long long* cand = isBot ? candB : candT;
        for (int it = 0; it < 20; ++it) {
            unsigned long long best = key[0]; int bi = 0;
#pragma unroll
            for (int i = 1; i < 8; ++i) if (key[i] > best) { best = key[i]; bi = i; }
            unsigned long long wbest = best;
#pragma unroll
            for (int o = 16; o; o >>= 1) {
                unsigned long long oth = __shfl_xor_sync(0xffffffffu, wbest, o);
                if (oth > wbest) wbest = oth;
            }
            if (best == wbest) key[bi] = 0ull;   // keys unique -> exactly one owner
            if (lane == 0) cand[sw * 20 + it] = wbest;
        }
    }
    __syncthreads();   // red[], candT/candB ready

    if (t < 40) {
        float s = 0.f;
#pragma unroll
        for (int w = 0; w < 8; ++w) s += red[t][w];
        Rall[t] = s;
    }
    // merge 80 candidates -> global top/bottom 20 (warp 0 and warp 4)
    if (wid == 0 || wid == 4) {
        const bool isBot = (wid == 4);
        const unsigned long long* cand = isBot ? candB : candT;
        unsigned long long k0 = cand[lane];
        unsigned long long k1 = cand[lane + 32];
        unsigned long long k2 = (lane < 16) ? cand[lane + 64] : 0ull;
        for (int it = 0; it < 20; ++it) {
            unsigned long long best = k0; int bi = 0;
            if (k1 > best) { best = k1; bi = 1; }
            if (k2 > best) { best = k2; bi = 2; }
            unsigned long long wbest = best;
#pragma unroll
            for (int o = 16; o; o >>= 1) {
                unsigned long long oth = __shfl_xor_sync(0xffffffffu, wbest, o);
                if (oth > wbest) wbest = oth;
            }
            if (best == wbest) { if (bi == 0) k0 = 0ull; else if (bi == 1) k1 = 0ull; else k2 = 0ull; }
            if (lane == 0) {
                const int m = 1023 - (int)(unsigned)wbest;
                if (!isBot) { tk[it] = kk[m]; tv[it] = vv[m]; }
                else        { bk[it] = kk[m]; bv[it] = vv[m]; }
            }
        }
    }
    __syncthreads();

    if (t < NC) {
        const float f = c_invf[t];
        coefD[t]  = Rall[t] * f;
        coefS1[t] = Rall[t + 1] * f;
        coefDg[t] = Rall[14 + t] * f;
        coefSv[t] = Rall[27 + t] * f;
    }
    __syncthreads();

    // ---- entropy + global attention (this block's 512 rows) ----
    float ent = 0.f;
#pragma unroll
    for (int ii = 0; ii < 2; ++ii) {
        const int i = t + ii * NT;
        const int n = half * 512 + i;
        const float a = qs[i] * SCALE;
        const float D = horner13s(coefD, a);
        const float S1 = horner13s(coefS1, a);
        ent += __logf(D) - a * S1 / D;
        const float ag = gqs[i] * SCALE;
        g_gx[n * 64 + h] = horner13s(coefSv, ag) / horner13s(coefDg, ag);
    }
    for (int o = 16; o; o >>= 1) ent += __shfl_down_sync(0xffffffffu, ent, o);
    if (lane == 0) red[0][wid] = ent;
    __syncthreads();
    if (t == 0) {
        float s = 0.f;
#pragma unroll
        for (int w = 0; w < 8; ++w) s += red[0][w];
        g_entpart[b] = s;
    }

    gridbar(1);

    if (t == 0) {   // identical, fixed-order in every block -> deterministic
        float s = 0.f;
#pragma unroll 8
        for (int bb = 0; bb < NB; ++bb) s += g_entpart[bb];
        const float em = s * (1.f / (float)(NH * NN));
        int km = 5 + (int)rintf(15.f * em);
        if (km < 5) km = 5;
        if (km > 20) km = 20;
        km_s = km;
    }
    __syncthreads();
    const int km = km_s;

    if (t < NC) {   // Taylor coeffs of local numerator for both sign branches
        float sp = 0.f, sn = 0.f;
        for (int i = 0; i < km; ++i) {
            float pp = 1.f, pn = 1.f;
            for (int jj = 0; jj < t; ++jj) { pp *= tk[i]; pn *= bk[i]; }
            sp += tv[i] * pp;
            sn += bv[i] * pn;
        }
        cLp[t] = sp * c_invf[t];
        cLn[t] = sn * c_invf[t];
    }
    __syncthreads();

    // ---- local attention (this block's 512 rows) ----
#pragma unroll
    for (int ii = 0; ii < 2; ++ii) {
        const int i = t + ii * NT;
        const int n = half * 512 + i;
        const float a = qs[i] * SCALE;
        const float D = horner13s(coefD, a);
        float num;
        if (a > 0.f)      num = horner13s(cLp, a);
        else if (a < 0.f) num = horner13s(cLn, a);
        else { num = 0.f; for (int m = 0; m < km; ++m) num += vv[m]; }
        g_lx[n * 64 + h] = num / D;
    }

    gridbar(2);

    // ================= Phase C: fuse + residual + proj (8 rows) =================
    float* lxS = kk;
    float* gxS = gk;
    float* ttS = vv;
#pragma unroll
    for (int ii = 0; ii < 2; ++ii) {
        const int i = t + ii * NT;
        lxS[i] = g_lx[n0 * 64 + i];
        gxS[i] = g_gx[n0 * 64 + i];
    }
    if (t < 64) {   // importance / early flag (identical per block)
        float cs = 0.f;
#pragma unroll 8
        for (int bb = 0; bb < NB; ++bb) cs += g_xpart[bb][t];
        sred[t] = cs * (1.f / (float)NN) * hg_w[t];
    }
    __syncthreads();
    if (t == 0) {
        float l = hg_b[0];
#pragma unroll
        for (int j = 0; j < 64; ++j) l += sred[j];
        const float imp = 1.f / (1.f + expf(-l));
        early_s = (imp < 0.1f) ? 1 : 0;
    }

    const int c = t & 63;
#pragma unroll
    for (int rr = 0; rr < 2; ++rr) {
        const int r = (t >> 6) + rr * 4;
        float f = fus_b[c];
#pragma unroll 8
        for (int j = 0; j < 64; ++j) f = fmaf(lxS[r * 64 + j], fus_w[j * 64 + c], f);
#pragma unroll 8
        for (int j = 0; j < 64; ++j) f = fmaf(gxS[r * 64 + j], fus_w[(64 + j) * 64 + c], f);
        ttS[r * 64 + c] = xmS[r * 64 + c] + f;
    }
    __syncthreads();
    const int early = early_s;
#pragma unroll
    for (int rr = 0; rr < 2; ++rr) {
        const int r = (t >> 6) + rr * 4;
        float o = proj_b[c];
#pragma unroll 8
        for (int j = 0; j < 64; ++j) o = fmaf(ttS[r * 64 + j], proj_w[j * 64 + c], o);
        out[(n0 + r) * 64 + c] = early ? xs[r * 64 + c] : o;
    }
}

extern "C" void kernel_launch(void* const* d_in, const int* in_sizes, int n_in,
                              void* d_out, int out_size) {
    const float* x      = (const float*)d_in[0];
    const float* qkv_w  = (const float*)d_in[1];
    const float* qkv_b  = (const float*)d_in[2];
    const float* gqkv_w = (const float*)d_in[3];
    const float* gqkv_b = (const float*)d_in[4];
    const float* cg_w   = (const float*)d_in[5];
    const float* cg_b   = (const float*)d_in[6];
    const float* hg_w   = (const float*)d_in[7];
    const float* hg_b   = (const float*)d_in[8];
    const float* fus_w  = (const float*)d_in[9];
    const float* fus_b  = (const float*)d_in[10];
    const float* proj_w = (const float*)d_in[11];
    const float* proj_b = (const float*)d_in[12];
    float* out = (float*)d_out;

    fused_kernel<<<NB, NT>>>(x, qkv_w, qkv_b, gqkv_w, gqkv_b, cg_w, cg_b,
                             hg_w, hg_b, fus_w, fus_b, proj_w, proj_b, out);
}

// round 4
// speedup vs baseline: 1.4920x; 1.1293x over previous
#include <cuda_runtime.h>
#include <math.h>

#define NN 1024
#define NH 64
#define NC 13
#define SCALE 0.125f
#define KMAX 20
#define NB 256
#define NT 256
#define RPB 4             // rows per block (NN/NB)
#define GATE_THR (-2.1972245773362196f)   // logit(0.1)

// -------- device scratch --------
__device__ float g_q[NH][NN], g_k[NH][NN], g_v[NH][NN];
__device__ float g_gq[NH][NN], g_gk[NH][NN], g_gv[NH][NN];
__device__ float g_xpart[NB][64];
__device__ float g_entpart[NB];
__device__ float g_lx[NN * 64];
__device__ float g_gx[NN * 64];
__device__ unsigned g_barcnt[4];   // zero-init; monotonic across graph replays

__constant__ float c_invf[14] = {
    1.0f, 1.0f, 0.5f, 1.66666672e-01f, 4.16666679e-02f, 8.33333377e-03f,
    1.38888892e-03f, 1.98412701e-04f, 2.48015876e-05f, 2.75573188e-06f,
    2.75573192e-07f, 2.50521084e-08f, 2.08767563e-09f, 1.60590438e-10f };

__device__ __forceinline__ unsigned ford(float f) {
    unsigned u = __float_as_uint(f);
    return (u & 0x80000000u) ? ~u : (u | 0x80000000u);
}

__device__ __forceinline__ float horner13s(const float* c, float a) {
    float r = c[12];
#pragma unroll
    for (int j = 11; j >= 0; --j) r = fmaf(r, a, c[j]);
    return r;
}

__device__ __forceinline__ void gridbar(int idx) {
    __syncthreads();
    if (threadIdx.x == 0) {
        __threadfence();
        unsigned my = atomicAdd(&g_barcnt[idx], 1u);
        unsigned target = (my / (unsigned)NB + 1u) * (unsigned)NB;
        while (*(volatile unsigned*)&g_barcnt[idx] < target) { __nanosleep(32); }
        __threadfence();
    }
    __syncthreads();
}

__global__ __launch_bounds__(NT, 2)
void fused_kernel(const float* __restrict__ x,
                  const float* __restrict__ qkv_w,  const float* __restrict__ qkv_b,
                  const float* __restrict__ gqkv_w, const float* __restrict__ gqkv_b,
                  const float* __restrict__ cg_w,   const float* __restrict__ cg_b,
                  const float* __restrict__ hg_w,   const float* __restrict__ hg_b,
                  const float* __restrict__ fus_w,  const float* __restrict__ fus_b,
                  const float* __restrict__ proj_w, const float* __restrict__ proj_b,
                  float* __restrict__ out) {
    __shared__ float xs[RPB * 64];     // original x rows (persists A->C)
    __shared__ float xmS[RPB * 64];    // masked x rows (persists A->C)
    __shared__ float qs[256], gqs[256];
    __shared__ float kk[NN], vv[NN], gk[NN], gv[NN];
    __shared__ unsigned long long candT[80], candB[80];
    __shared__ float red[40][8];
    __shared__ float Rall[40];
    __shared__ float coefD[NC], coefS1[NC], coefDg[NC], coefSv[NC];
    __shared__ float tk[KMAX], tv[KMAX], bk[KMAX], bv[KMAX];
    __shared__ float cLp[NC], cLn[NC];
    __shared__ float spart[4][64];
    __shared__ float sred[64];
    __shared__ int   km_s, early_s;

    const int b = blockIdx.x;
    const int t = threadIdx.x;
    const int lane = t & 31, wid = t >> 5;
    const int n0 = b * RPB;

    // ================= Phase A: gate + qkv/gqkv GEMMs (4 rows) =================
    xs[t] = x[n0 * 64 + t];            // RPB*64 == NT
    __syncthreads();

    if (t < 64) {
        float s = 0.f;
#pragma unroll
        for (int r = 0; r < RPB; ++r) s += xs[r * 64 + t];
        g_xpart[b][t] = s;
    }

    {   // content gate: 256 outputs, 1 per thread
        const int c = t & 63, r = t >> 6;
        float l = cg_b[c];
#pragma unroll
        for (int j = 0; j < 64; ++j) l = fmaf(xs[r * 64 + j], cg_w[j * 64 + c], l);
        xmS[r * 64 + c] = (l > (float)GATE_THR) ? xs[r * 64 + c] : 0.f;
    }
    __syncthreads();

    // qkv (192 cols) + gqkv (192 cols): 4-row register tile per column-thread
    for (int cc = t; cc < 384; cc += NT) {
        const bool isg = (cc >= 192);
        const int c = isg ? cc - 192 : cc;
        const float* wp = isg ? gqkv_w : qkv_w;
        float acc[RPB];
        const float bias = isg ? gqkv_b[c] : qkv_b[c];
#pragma unroll
        for (int r = 0; r < RPB; ++r) acc[r] = bias;
#pragma unroll 16
        for (int j = 0; j < 64; ++j) {
            const float w = wp[j * 192 + c];
#pragma unroll
            for (int r = 0; r < RPB; ++r) acc[r] = fmaf(xmS[r * 64 + j], w, acc[r]);
        }
        const int h = c & 63, part = c >> 6;
        float* dst = isg ? (part == 0 ? g_gq[h] : part == 1 ? g_gk[h] : g_gv[h])
                         : (part == 0 ? g_q[h]  : part == 1 ? g_k[h]  : g_v[h]);
        *(float4*)(dst + n0) = make_float4(acc[0], acc[1], acc[2], acc[3]);
    }

    gridbar(0);

    // ================= Phase B: head h, quarter of rows =================
    const int h = b >> 2, qtr = b & 3;
#pragma unroll
    for (int ii = 0; ii < 4; ++ii) {
        const int i = t + ii * NT;
        kk[i] = g_k[h][i];  vv[i] = g_v[h][i];
        gk[i] = g_gk[h][i]; gv[i] = g_gv[h][i];
    }
    qs[t]  = g_q[h][qtr * 256 + t];
    gqs[t] = g_gq[h][qtr * 256 + t];
    __syncthreads();

    // ---- moments ----
    {
        float M[14], Mg[NC], Wg[NC];
#pragma unroll
        for (int j = 0; j < 14; ++j) M[j] = 0.f;
#pragma unroll
        for (int j = 0; j < NC; ++j) { Mg[j] = 0.f; Wg[j] = 0.f; }
#pragma unroll
        for (int ii = 0; ii < 4; ++ii) {
            const int m = t + ii * NT;
            const float kv = kk[m];
            float p = 1.f;
#pragma unroll
            for (int j = 0; j < 14; ++j) { M[j] += p; p *= kv; }
            const float gkv = gk[m], gvv = gv[m];
            float pg = 1.f;
#pragma unroll
            for (int j = 0; j < NC; ++j) { Mg[j] += pg; Wg[j] += gvv * pg; pg *= gkv; }
        }
#pragma unroll
        for (int j = 0; j < 14; ++j) {
            float v = M[j];
            for (int o = 16; o; o >>= 1) v += __shfl_down_sync(0xffffffffu, v, o);
            if (lane == 0) red[j][wid] = v;
        }
#pragma unroll
        for (int j = 0; j < NC; ++j) {
            float v = Mg[j];
            for (int o = 16; o; o >>= 1) v += __shfl_down_sync(0xffffffffu, v, o);
            if (lane == 0) red[14 + j][wid] = v;
            float w = Wg[j];
            for (int o = 16; o; o >>= 1) w += __shfl_down_sync(0xffffffffu, w, o);
            if (lane == 0) red[27 + j][wid] = w;
        }
    }

    // ---- warp-select: warps 0-3 top-20, warps 4-7 bottom-20 (no barriers) ----
    {
        const int sw = wid & 3;
        const bool isBot = (wid >= 4);
        unsigned long long key[8];
#pragma unroll
        for (int i = 0; i < 8; ++i) {
            const int m = sw * 256 + i * 32 + lane;
            unsigned f = ford(kk[m]);
            if (isBot) f = ~f;
            key[i] = ((unsigned long long)f << 32) | (unsigned)(1023 - m);
        }
        unsigned long long* cand = isBot ? candB : candT;
        for (int it = 0; it < 20; ++it) {
            unsigned long long best = key[0]; int bi = 0;
#pragma unroll
            for (int i = 1; i < 8; ++i) if (key[i] > best) { best = key[i]; bi = i; }
            unsigned long long wbest = best;
#pragma unroll
            for (int o = 16; o; o >>= 1) {
                unsigned long long oth = __shfl_xor_sync(0xffffffffu, wbest, o);
                if (oth > wbest) wbest = oth;
            }
            if (best == wbest) key[bi] = 0ull;   // keys unique -> one owner
            if (lane == 0) cand[sw * 20 + it] = wbest;
        }
    }
    __syncthreads();   // red[], candT/candB ready

    if (t < 40) {
        float s = 0.f;
#pragma unroll
        for (int w = 0; w < 8; ++w) s += red[t][w];
        Rall[t] = s;
    }
    // merge 80 candidates -> global top/bottom 20 (warp 0 and warp 4)
    if (wid == 0 || wid == 4) {
        const bool isBot = (wid == 4);
        const unsigned long long* cand = isBot ? candB : candT;
        unsigned long long k0 = cand[lane];
        unsigned long long k1 = cand[lane + 32];
        unsigned long long k2 = (lane < 16) ? cand[lane + 64] : 0ull;
        for (int it = 0; it < 20; ++it) {
            unsigned long long best = k0; int bi = 0;
            if (k1 > best) { best = k1; bi = 1; }
            if (k2 > best) { best = k2; bi = 2; }
            unsigned long long wbest = best;
#pragma unroll
            for (int o = 16; o; o >>= 1) {
                unsigned long long oth = __shfl_xor_sync(0xffffffffu, wbest, o);
                if (oth > wbest) wbest = oth;
            }
            if (best == wbest) { if (bi == 0) k0 = 0ull; else if (bi == 1) k1 = 0ull; else k2 = 0ull; }
            if (lane == 0) {
                const int m = 1023 - (int)(unsigned)wbest;
                if (!isBot) { tk[it] = kk[m]; tv[it] = vv[m]; }
                else        { bk[it] = kk[m]; bv[it] = vv[m]; }
            }
        }
    }
    __syncthreads();

    if (t < NC) {
        const float f = c_invf[t];
        coefD[t]  = Rall[t] * f;
        coefS1[t] = Rall[t + 1] * f;
        coefDg[t] = Rall[14 + t] * f;
        coefSv[t] = Rall[27 + t] * f;
    }
    __syncthreads();

    // ---- entropy + global attention (this block's 256 rows, 1/thread) ----
    {
        const int n = qtr * 256 + t;
        const float a = qs[t] * SCALE;
        const float D = horner13s(coefD, a);
        const float S1 = horner13s(coefS1, a);
        float ent = __logf(D) - a * S1 / D;
        const float ag = gqs[t] * SCALE;
        g_gx[n * 64 + h] = horner13s(coefSv, ag) / horner13s(coefDg, ag);
        for (int o = 16; o; o >>= 1) ent += __shfl_down_sync(0xffffffffu, ent, o);
        if (lane == 0) red[0][wid] = ent;
    }
    __syncthreads();
    if (t == 0) {
        float s = 0.f;
#pragma unroll
        for (int w = 0; w < 8; ++w) s += red[0][w];
        g_entpart[b] = s;
    }

    gridbar(1);

    // km: warp 0, fixed lane-strided order (identical in every block)
    if (wid == 0) {
        float s = 0.f;
#pragma unroll
        for (int i = 0; i < 8; ++i) s += g_entpart[lane * 8 + i];
        for (int o = 16; o; o >>= 1) s += __shfl_down_sync(0xffffffffu, s, o);
        if (lane == 0) {
            const float em = s * (1.f / (float)(NH * NN));
            int km = 5 + (int)rintf(15.f * em);
            if (km < 5) km = 5;
            if (km > 20) km = 20;
            km_s = km;
        }
    }
    __syncthreads();
    const int km = km_s;

    if (t < NC) {   // Taylor coeffs of local numerator, both sign branches
        float sp = 0.f, sn = 0.f;
        for (int i = 0; i < km; ++i) {
            float pp = 1.f, pn = 1.f;
            for (int jj = 0; jj < t; ++jj) { pp *= tk[i]; pn *= bk[i]; }
            sp += tv[i] * pp;
            sn += bv[i] * pn;
        }
        cLp[t] = sp * c_invf[t];
        cLn[t] = sn * c_invf[t];
    }
    __syncthreads();

    // ---- local attention (this block's 256 rows, 1/thread) ----
    {
        const int n = qtr * 256 + t;
        const float a = qs[t] * SCALE;
        const float D = horner13s(coefD, a);
        float num;
        if (a > 0.f)      num = horner13s(cLp, a);
        else if (a < 0.f) num = horner13s(cLn, a);
        else { num = 0.f; for (int m = 0; m < km; ++m) num += vv[m]; }
        g_lx[n * 64 + h] = num / D;
    }

    gridbar(2);

    // ================= Phase C: fuse + residual + proj (4 rows) =================
    float* lxS = kk;
    float* gxS = gk;
    float* ttS = vv;
    lxS[t] = g_lx[n0 * 64 + t];
    gxS[t] = g_gx[n0 * 64 + t];

    {   // importance (two-stage fixed-order over 256 blocks)
        const int c = t & 63, seg = t >> 6;
        float p = 0.f;
#pragma unroll 16
        for (int i = 0; i < 64; ++i) p += g_xpart[seg * 64 + i][c];
        spart[seg][c] = p;
    }
    __syncthreads();
    if (t < 64) {
        float cs = spart[0][t] + spart[1][t] + spart[2][t] + spart[3][t];
        sred[t] = cs * (1.f / (float)NN) * hg_w[t];
    }
    __syncthreads();
    if (t == 0) {
        float l = hg_b[0];
#pragma unroll
        for (int j = 0; j < 64; ++j) l += sred[j];
        const float imp = 1.f / (1.f + expf(-l));
        early_s = (imp < 0.1f) ? 1 : 0;
    }

    const int c = t & 63, r = t >> 6;
    {
        float f = fus_b[c];
#pragma unroll 16
        for (int j = 0; j < 64; ++j) f = fmaf(lxS[r * 64 + j], fus_w[j * 64 + c], f);
#pragma unroll 16
        for (int j = 0; j < 64; ++j) f = fmaf(gxS[r * 64 + j], fus_w[(64 + j) * 64 + c], f);
        ttS[r * 64 + c] = xmS[r * 64 + c] + f;
    }
    __syncthreads();
    const int early = early_s;
    {
        float o = proj_b[c];
#pragma unroll 16
        for (int j = 0; j < 64; ++j) o = fmaf(ttS[r * 64 + j], proj_w[j * 64 + c], o);
        out[(n0 + r) * 64 + c] = early ? xs[r * 64 + c] : o;
    }
}

extern "C" void kernel_launch(void* const* d_in, const int* in_sizes, int n_in,
                              void* d_out, int out_size) {
    const float* x      = (const float*)d_in[0];
    const float* qkv_w  = (const float*)d_in[1];
    const float* qkv_b  = (const float*)d_in[2];
    const float* gqkv_w = (const float*)d_in[3];
    const float* gqkv_b = (const float*)d_in[4];
    const float* cg_w   = (const float*)d_in[5];
    const float* cg_b   = (const float*)d_in[6];
    const float* hg_w   = (const float*)d_in[7];
    const float* hg_b   = (const float*)d_in[8];
    const float* fus_w  = (const float*)d_in[9];
    const float* fus_b  = (const float*)d_in[10];
    const float* proj_w = (const float*)d_in[11];
    const float* proj_b = (const float*)d_in[12];
    float* out = (float*)d_out;

    fused_kernel<<<NB, NT>>>(x, qkv_w, qkv_b, gqkv_w, gqkv_b, cg_w, cg_b,
                             hg_w, hg_b, fus_w, fus_b, proj_w, proj_b, out);
}

// round 5
// speedup vs baseline: 1.7529x; 1.1749x over previous
#include <cuda_runtime.h>
#include <math.h>

#define NN 1024
#define NH 64
#define NC 10             // Taylor terms (degree 9)
#define SCALE 0.125f
#define KMAX 20
#define NB 256
#define NT 256
#define RPB 4
#define GATE_THR (-2.1972245773362196f)   // logit(0.1)

// -------- device scratch --------
__device__ float g_q[NH][NN], g_k[NH][NN], g_v[NH][NN];
__device__ float g_gq[NH][NN], g_gk[NH][NN], g_gv[NH][NN];
__device__ float g_xpart[NB][64];
__device__ float g_entpart[NB];
__device__ float g_gx[NN * 64];
__device__ float g_hdD[NH][NC];       // per-head denominator coefs
__device__ float g_tk[NH][KMAX], g_tv[NH][KMAX];
__device__ float g_bk[NH][KMAX], g_bv[NH][KMAX];
__device__ float g_vpre[NH][KMAX];    // prefix sums of v[0..19]
__device__ unsigned g_barcnt[4];      // zero-init; monotonic across replays

__constant__ float c_invf[NC] = {
    1.0f, 1.0f, 0.5f, 1.66666672e-01f, 4.16666679e-02f, 8.33333377e-03f,
    1.38888892e-03f, 1.98412701e-04f, 2.48015876e-05f, 2.75573188e-06f };

__device__ __forceinline__ unsigned ford(float f) {
    unsigned u = __float_as_uint(f);
    return (u & 0x80000000u) ? ~u : (u | 0x80000000u);
}

__device__ __forceinline__ float horner10(const float* c, float a) {
    float r = c[NC - 1];
#pragma unroll
    for (int j = NC - 2; j >= 0; --j) r = fmaf(r, a, c[j]);
    return r;
}

__device__ __forceinline__ void gridbar(int idx) {
    __syncthreads();
    if (threadIdx.x == 0) {
        __threadfence();
        unsigned my = atomicAdd(&g_barcnt[idx], 1u);
        unsigned target = (my / (unsigned)NB + 1u) * (unsigned)NB;
        while (*(volatile unsigned*)&g_barcnt[idx] < target) { __nanosleep(32); }
        __threadfence();
    }
    __syncthreads();
}

__global__ __launch_bounds__(NT, 2)
void fused_kernel(const float* __restrict__ x,
                  const float* __restrict__ qkv_w,  const float* __restrict__ qkv_b,
                  const float* __restrict__ gqkv_w, const float* __restrict__ gqkv_b,
                  const float* __restrict__ cg_w,   const float* __restrict__ cg_b,
                  const float* __restrict__ hg_w,   const float* __restrict__ hg_b,
                  const float* __restrict__ fus_w,  const float* __restrict__ fus_b,
                  const float* __restrict__ proj_w, const float* __restrict__ proj_b,
                  float* __restrict__ out) {
    __shared__ float xs[RPB * 64];     // persists A->C
    __shared__ float xmS[RPB * 64];    // persists A->C
    __shared__ float qsS[RPB * 64];    // q for this block's rows (persists A->C)
    __shared__ float kk[NN], vv[NN], gk[NN], gv[NN];   // B; reused in C
    __shared__ float qs[256], gqs[256];
    __shared__ unsigned long long candT[80], candB[80];
    __shared__ float red[32][8];
    __shared__ float Rall[32];
    __shared__ float coefD[NC], coefS1[NC], coefDg[NC], coefSv[NC];
    __shared__ float tkS[KMAX], tvS[KMAX], bkS[KMAX], bvS[KMAX];
    __shared__ float spart[4][64];
    __shared__ float sred[64];
    __shared__ int   km_s, early_s;

    const int b = blockIdx.x;
    const int t = threadIdx.x;
    const int lane = t & 31, wid = t >> 5;
    const int n0 = b * RPB;

    // ================= Phase A: gate + qkv/gqkv GEMMs (4 rows) =================
    xs[t] = x[n0 * 64 + t];
    __syncthreads();

    if (t < 64) {
        float s = 0.f;
#pragma unroll
        for (int r = 0; r < RPB; ++r) s += xs[r * 64 + t];
        g_xpart[b][t] = s;
    }
    {   // content gate
        const int c = t & 63, r = t >> 6;
        float l = cg_b[c];
#pragma unroll
        for (int j = 0; j < 64; ++j) l = fmaf(xs[r * 64 + j], cg_w[j * 64 + c], l);
        xmS[r * 64 + c] = (l > (float)GATE_THR) ? xs[r * 64 + c] : 0.f;
    }
    __syncthreads();

    for (int cc = t; cc < 384; cc += NT) {
        const bool isg = (cc >= 192);
        const int c = isg ? cc - 192 : cc;
        const float* wp = isg ? gqkv_w : qkv_w;
        float acc[RPB];
        const float bias = isg ? gqkv_b[c] : qkv_b[c];
#pragma unroll
        for (int r = 0; r < RPB; ++r) acc[r] = bias;
#pragma unroll 16
        for (int j = 0; j < 64; ++j) {
            const float w = wp[j * 192 + c];
#pragma unroll
            for (int r = 0; r < RPB; ++r) acc[r] = fmaf(xmS[r * 64 + j], w, acc[r]);
        }
        const int h = c & 63, part = c >> 6;
        if (!isg && part == 0) {
#pragma unroll
            for (int r = 0; r < RPB; ++r) qsS[r * 64 + h] = acc[r];
        }
        float* dst = isg ? (part == 0 ? g_gq[h] : part == 1 ? g_gk[h] : g_gv[h])
                         : (part == 0 ? g_q[h]  : part == 1 ? g_k[h]  : g_v[h]);
        *(float4*)(dst + n0) = make_float4(acc[0], acc[1], acc[2], acc[3]);
    }

    gridbar(0);

    // ================= Phase B: head stats + entropy + global attn =================
    const int h = b >> 2, qtr = b & 3;
#pragma unroll
    for (int ii = 0; ii < 4; ++ii) {
        const int i = t + ii * NT;
        kk[i] = g_k[h][i];
        gk[i] = g_gk[h][i]; gv[i] = g_gv[h][i];
    }
    if (qtr == 1) {
#pragma unroll
        for (int ii = 0; ii < 4; ++ii) { const int i = t + ii * NT; vv[i] = g_v[h][i]; }
    }
    qs[t]  = g_q[h][qtr * 256 + t];
    gqs[t] = g_gq[h][qtr * 256 + t];
    __syncthreads();

    // ---- moments: k^0..k^(NC+1), gk^0..gk^(NC-1), gv*gk^0.. ----
    {
        float M[NC + 2], Mg[NC], Wg[NC];
#pragma unroll
        for (int j = 0; j < NC + 2; ++j) M[j] = 0.f;
#pragma unroll
        for (int j = 0; j < NC; ++j) { Mg[j] = 0.f; Wg[j] = 0.f; }
#pragma unroll
        for (int ii = 0; ii < 4; ++ii) {
            const int m = t + ii * NT;
            const float kv = kk[m];
            float p = 1.f;
#pragma unroll
            for (int j = 0; j < NC + 2; ++j) { M[j] += p; p *= kv; }
            const float gkv = gk[m], gvv = gv[m];
            float pg = 1.f;
#pragma unroll
            for (int j = 0; j < NC; ++j) { Mg[j] += pg; Wg[j] += gvv * pg; pg *= gkv; }
        }
#pragma unroll
        for (int j = 0; j < NC + 2; ++j) {
            float v = M[j];
            for (int o = 16; o; o >>= 1) v += __shfl_down_sync(0xffffffffu, v, o);
            if (lane == 0) red[j][wid] = v;
        }
#pragma unroll
        for (int j = 0; j < NC; ++j) {
            float v = Mg[j];
            for (int o = 16; o; o >>= 1) v += __shfl_down_sync(0xffffffffu, v, o);
            if (lane == 0) red[NC + 2 + j][wid] = v;
            float w = Wg[j];
            for (int o = 16; o; o >>= 1) w += __shfl_down_sync(0xffffffffu, w, o);
            if (lane == 0) red[2 * NC + 2 + j][wid] = w;
        }
    }

    // ---- select (only qtr==1 blocks): top-20 & bottom-20 ----
    if (qtr == 1) {
        {
            const int sw = wid & 3;
            const bool isBot = (wid >= 4);
            unsigned long long key[8];
#pragma unroll
            for (int i = 0; i < 8; ++i) {
                const int m = sw * 256 + i * 32 + lane;
                unsigned f = ford(kk[m]);
                if (isBot) f = ~f;
                key[i] = ((unsigned long long)f << 32) | (unsigned)(1023 - m);
            }
            unsigned long long* cand = isBot ? candB : candT;
            for (int it = 0; it < 20; ++it) {
                unsigned long long best = key[0]; int bi = 0;
#pragma unroll
                for (int i = 1; i < 8; ++i) if (key[i] > best) { best = key[i]; bi = i; }
                unsigned long long wbest = best;
#pragma unroll
                for (int o = 16; o; o >>= 1) {
                    unsigned long long oth = __shfl_xor_sync(0xffffffffu, wbest, o);
                    if (oth > wbest) wbest = oth;
                }
                if (best == wbest) key[bi] = 0ull;
                if (lane == 0) cand[sw * 20 + it] = wbest;
            }
        }
        __syncthreads();
        if (wid == 0 || wid == 4) {
            const bool isBot = (wid == 4);
            const unsigned long long* cand = isBot ? candB : candT;
            unsigned long long k0 = cand[lane];
            unsigned long long k1 = cand[lane + 32];
            unsigned long long k2 = (lane < 16) ? cand[lane + 64] : 0ull;
            for (int it = 0; it < 20; ++it) {
                unsigned long long best = k0; int bi = 0;
                if (k1 > best) { best = k1; bi = 1; }
                if (k2 > best) { best = k2; bi = 2; }
                unsigned long long wbest = best;
#pragma unroll
                for (int o = 16; o; o >>= 1) {
                    unsigned long long oth = __shfl_xor_sync(0xffffffffu, wbest, o);
                    if (oth > wbest) wbest = oth;
                }
                if (best == wbest) { if (bi == 0) k0 = 0ull; else if (bi == 1) k1 = 0ull; else k2 = 0ull; }
                if (lane == 0) {
                    const int m = 1023 - (int)(unsigned)wbest;
                    if (!isBot) { tkS[it] = kk[m]; tvS[it] = vv[m]; }
                    else        { bkS[it] = kk[m]; bvS[it] = vv[m]; }
                }
            }
        }
    }
    __syncthreads();

    if (t < 32) {
        float s = 0.f;
#pragma unroll
        for (int w = 0; w < 8; ++w) s += red[t][w];
        Rall[t] = s;
    }
    __syncthreads();
    if (t < NC) {
        const float f = c_invf[t];
        coefD[t]  = Rall[t] * f;
        coefS1[t] = Rall[t + 1] * f;
        coefDg[t] = Rall[NC + 2 + t] * f;
        coefSv[t] = Rall[2 * NC + 2 + t] * f;
        if (qtr == 0) g_hdD[h][t] = coefD[t];
    }
    if (qtr == 1) {
        if (t < KMAX) {
            g_tk[h][t] = tkS[t]; g_tv[h][t] = tvS[t];
            g_bk[h][t] = bkS[t]; g_bv[h][t] = bvS[t];
        }
        if (t == 0) {
            float s = 0.f;
            for (int i = 0; i < KMAX; ++i) { s += vv[i]; g_vpre[h][i] = s; }
        }
    }
    __syncthreads();

    // ---- entropy + global attention (256 rows, 1/thread) ----
    {
        const int n = qtr * 256 + t;
        const float a = qs[t] * SCALE;
        const float D = horner10(coefD, a);
        const float S1 = horner10(coefS1, a);
        float ent = __logf(D) - a * S1 / D;
        const float ag = gqs[t] * SCALE;
        g_gx[n * 64 + h] = horner10(coefSv, ag) / horner10(coefDg, ag);
        for (int o = 16; o; o >>= 1) ent += __shfl_down_sync(0xffffffffu, ent, o);
        if (lane == 0) red[0][wid] = ent;
    }
    __syncthreads();
    if (t == 0) {
        float s = 0.f;
#pragma unroll
        for (int w = 0; w < 8; ++w) s += red[0][w];
        g_entpart[b] = s;
    }

    gridbar(1);

    // ================= Phase C: km, local attn, fuse, proj =================
    float* cDs = kk;          // [64][NC] = 640
    float* cLp = vv;          // [64][NC]
    float* cLn = gk;          // [64][NC]
    float* lxS = gv;          // [0..255]
    float* gxS = gv + 256;    // [256..511]
    float* ttS = gv + 512;    // [512..767]

    // km: warp 0 fixed-order (identical in every block)
    if (wid == 0) {
        float s = 0.f;
#pragma unroll
        for (int i = 0; i < 8; ++i) s += g_entpart[lane * 8 + i];
        for (int o = 16; o; o >>= 1) s += __shfl_down_sync(0xffffffffu, s, o);
        if (lane == 0) {
            const float em = s * (1.f / (float)(NH * NN));
            int km = 5 + (int)rintf(15.f * em);
            if (km < 5) km = 5;
            if (km > 20) km = 20;
            km_s = km;
        }
    }
    // coalesced loads while warp 0 reduces
    for (int i = t; i < 64 * NC; i += NT) cDs[i] = (&g_hdD[0][0])[i];
    gxS[t] = g_gx[n0 * 64 + t];
    {   // importance partials
        const int c = t & 63, seg = t >> 6;
        float p = 0.f;
#pragma unroll 16
        for (int i = 0; i < 64; ++i) p += g_xpart[seg * 64 + i][c];
        spart[seg][c] = p;
    }
    __syncthreads();
    const int km = km_s;

    // build local-numerator Taylor coefs per (head, sign): threads 0..127
    if (t < 128) {
        const int hh = t & 63;
        const bool isBot = (t >= 64);
        const float* kp = isBot ? g_bk[hh] : g_tk[hh];
        const float* vp = isBot ? g_bv[hh] : g_tv[hh];
        float cl[NC];
#pragma unroll
        for (int j = 0; j < NC; ++j) cl[j] = 0.f;
        for (int i = 0; i < km; ++i) {
            const float kv = kp[i];
            float p = vp[i];
#pragma unroll
            for (int j = 0; j < NC; ++j) { cl[j] += p; p *= kv; }
        }
        float* dst = (isBot ? cLn : cLp) + hh * NC;
#pragma unroll
        for (int j = 0; j < NC; ++j) dst[j] = cl[j] * c_invf[j];
    }
    if (t < 64) {
        float cs = spart[0][t] + spart[1][t] + spart[2][t] + spart[3][t];
        sred[t] = cs * (1.f / (float)NN) * hg_w[t];
    }
    __syncthreads();
    if (t == 0) {
        float l = hg_b[0];
#pragma unroll
        for (int j = 0; j < 64; ++j) l += sred[j];
        const float imp = 1.f / (1.f + expf(-l));
        early_s = (imp < 0.1f) ? 1 : 0;
    }

    // local attention for this block's 4 rows x 64 heads (1/thread)
    {
        const int hh = t & 63, r = t >> 6;
        const float a = qsS[r * 64 + hh] * SCALE;
        const float D = horner10(cDs + hh * NC, a);
        float num;
        if (a > 0.f)      num = horner10(cLp + hh * NC, a);
        else if (a < 0.f) num = horner10(cLn + hh * NC, a);
        else              num = g_vpre[hh][km - 1];
        lxS[r * 64 + hh] = num / D;
    }
    __syncthreads();

    const int c = t & 63, r = t >> 6;
    {
        float f = fus_b[c];
#pragma unroll 16
        for (int j = 0; j < 64; ++j) f = fmaf(lxS[r * 64 + j], fus_w[j * 64 + c], f);
#pragma unroll 16
        for (int j = 0; j < 64; ++j) f = fmaf(gxS[r * 64 + j], fus_w[(64 + j) * 64 + c], f);
        ttS[r * 64 + c] = xmS[r * 64 + c] + f;
    }
    __syncthreads();
    const int early = early_s;
    {
        float o = proj_b[c];
#pragma unroll 16
        for (int j = 0; j < 64; ++j) o = fmaf(ttS[r * 64 + j], proj_w[j * 64 + c], o);
        out[(n0 + r) * 64 + c] = early ? xs[r * 64 + c] : o;
    }
}

extern "C" void kernel_launch(void* const* d_in, const int* in_sizes, int n_in,
                              void* d_out, int out_size) {
    const float* x      = (const float*)d_in[0];
    const float* qkv_w  = (const float*)d_in[1];
    const float* qkv_b  = (const float*)d_in[2];
    const float* gqkv_w = (const float*)d_in[3];
    const float* gqkv_b = (const float*)d_in[4];
    const float* cg_w   = (const float*)d_in[5];
    const float* cg_b   = (const float*)d_in[6];
    const float* hg_w   = (const float*)d_in[7];
    const float* hg_b   = (const float*)d_in[8];
    const float* fus_w  = (const float*)d_in[9];
    const float* fus_b  = (const float*)d_in[10];
    const float* proj_w = (const float*)d_in[11];
    const float* proj_b = (const float*)d_in[12];
    float* out = (float*)d_out;

    fused_kernel<<<NB, NT>>>(x, qkv_w, qkv_b, gqkv_w, gqkv_b, cg_w, cg_b,
                             hg_w, hg_b, fus_w, fus_b, proj_w, proj_b, out);
}

// round 6
// speedup vs baseline: 2.0353x; 1.1611x over previous
#include <cuda_runtime.h>
#include <math.h>

#define NN 1024
#define NH 64
#define NC 10             // Taylor terms (degree 9)
#define SCALE 0.125f
#define KMAX 20
#define NB 128
#define NT 512
#define RPB 8
#define GATE_THR (-2.1972245773362196f)   // logit(0.1)

// -------- device scratch --------
__device__ float g_q[NH][NN], g_k[NH][NN], g_v[NH][NN];
__device__ float g_gq[NH][NN], g_gk[NH][NN], g_gv[NH][NN];
__device__ float g_xpart[NB][64];
__device__ float g_entpart[NB];
__device__ float g_gx[NN * 64];
__device__ float g_hdD[NH][NC];
__device__ float g_tk[NH][KMAX], g_tv[NH][KMAX];
__device__ float g_bk[NH][KMAX], g_bv[NH][KMAX];
__device__ float g_vpre[NH][KMAX];
__device__ unsigned g_barcnt[4];      // zero-init; monotonic across replays

__constant__ float c_invf[NC] = {
    1.0f, 1.0f, 0.5f, 1.66666672e-01f, 4.16666679e-02f, 8.33333377e-03f,
    1.38888892e-03f, 1.98412701e-04f, 2.48015876e-05f, 2.75573188e-06f };

__device__ __forceinline__ unsigned ford(float f) {
    unsigned u = __float_as_uint(f);
    return (u & 0x80000000u) ? ~u : (u | 0x80000000u);
}

__device__ __forceinline__ float horner10(const float* c, float a) {
    float r = c[NC - 1];
#pragma unroll
    for (int j = NC - 2; j >= 0; --j) r = fmaf(r, a, c[j]);
    return r;
}

__device__ __forceinline__ void gridbar(int idx) {
    __syncthreads();
    if (threadIdx.x == 0) {
        __threadfence();
        unsigned my = atomicAdd(&g_barcnt[idx], 1u);
        unsigned target = (my / (unsigned)NB + 1u) * (unsigned)NB;
        while (*(volatile unsigned*)&g_barcnt[idx] < target) { __nanosleep(32); }
        __threadfence();
    }
    __syncthreads();
}

__global__ __launch_bounds__(NT, 1)
void fused_kernel(const float* __restrict__ x,
                  const float* __restrict__ qkv_w,  const float* __restrict__ qkv_b,
                  const float* __restrict__ gqkv_w, const float* __restrict__ gqkv_b,
                  const float* __restrict__ cg_w,   const float* __restrict__ cg_b,
                  const float* __restrict__ hg_w,   const float* __restrict__ hg_b,
                  const float* __restrict__ fus_w,  const float* __restrict__ fus_b,
                  const float* __restrict__ proj_w, const float* __restrict__ proj_b,
                  float* __restrict__ out) {
    __shared__ float xs[RPB * 64];     // persists A->C
    __shared__ float xmS[RPB * 64];    // persists A->C
    __shared__ float qsS[RPB * 64];    // q of this block's rows (persists A->C)
    __shared__ float kk[NN], vv[NN], gk[NN], gv[NN];   // B; reused as scratch in C
    __shared__ float qs[512], gqs[512];                // B; qs reused as ttS in C
    __shared__ unsigned long long candT[160], candB[160];
    __shared__ float red[32][16];
    __shared__ float Rall[32];
    __shared__ float coefD[NC], coefS1[NC], coefDg[NC], coefSv[NC];
    __shared__ float tkS[KMAX], tvS[KMAX], bkS[KMAX], bvS[KMAX];
    __shared__ float spart[8][64];
    __shared__ float sred[64];
    __shared__ int   km_s, early_s;

    const int b = blockIdx.x;
    const int t = threadIdx.x;
    const int lane = t & 31, wid = t >> 5;
    const int n0 = b * RPB;

    // ================= Phase A: gate + qkv/gqkv GEMMs (8 rows) =================
    xs[t] = x[n0 * 64 + t];            // RPB*64 == NT
    __syncthreads();

    if (t < 64) {
        float s = 0.f;
#pragma unroll
        for (int r = 0; r < RPB; ++r) s += xs[r * 64 + t];
        g_xpart[b][t] = s;
    }
    {   // content gate: 512 outputs, 1 per thread
        const int c = t & 63, r = t >> 6;
        float l = cg_b[c];
#pragma unroll
        for (int j = 0; j < 64; ++j) l = fmaf(xs[r * 64 + j], cg_w[j * 64 + c], l);
        xmS[r * 64 + c] = (l > (float)GATE_THR) ? xs[r * 64 + c] : 0.f;
    }
    __syncthreads();

    // qkv+gqkv: threads 0..383, one column each, 8-row register tile
    if (t < 384) {
        const bool isg = (t >= 192);
        const int c = isg ? t - 192 : t;
        const float* wp = isg ? gqkv_w : qkv_w;
        float acc[RPB];
        const float bias = isg ? gqkv_b[c] : qkv_b[c];
#pragma unroll
        for (int r = 0; r < RPB; ++r) acc[r] = bias;
#pragma unroll 16
        for (int j = 0; j < 64; ++j) {
            const float w = wp[j * 192 + c];
#pragma unroll
            for (int r = 0; r < RPB; ++r) acc[r] = fmaf(xmS[r * 64 + j], w, acc[r]);
        }
        const int h = c & 63, part = c >> 6;
        if (!isg && part == 0) {
#pragma unroll
            for (int r = 0; r < RPB; ++r) qsS[r * 64 + h] = acc[r];
        }
        float* dst = isg ? (part == 0 ? g_gq[h] : part == 1 ? g_gk[h] : g_gv[h])
                         : (part == 0 ? g_q[h]  : part == 1 ? g_k[h]  : g_v[h]);
        *(float4*)(dst + n0)     = make_float4(acc[0], acc[1], acc[2], acc[3]);
        *(float4*)(dst + n0 + 4) = make_float4(acc[4], acc[5], acc[6], acc[7]);
    }

    gridbar(0);

    // ================= Phase B: head stats + entropy + global attn =================
    const int h = b >> 1, half = b & 1;
#pragma unroll
    for (int ii = 0; ii < 2; ++ii) {
        const int i = t + ii * NT;
        kk[i] = g_k[h][i];
        gk[i] = g_gk[h][i]; gv[i] = g_gv[h][i];
    }
    if (half == 1) {
#pragma unroll
        for (int ii = 0; ii < 2; ++ii) { const int i = t + ii * NT; vv[i] = g_v[h][i]; }
    }
    qs[t]  = g_q[h][half * 512 + t];
    gqs[t] = g_gq[h][half * 512 + t];
    __syncthreads();

    // ---- moments (2 elements per thread) ----
    {
        float M[NC + 2], Mg[NC], Wg[NC];
#pragma unroll
        for (int j = 0; j < NC + 2; ++j) M[j] = 0.f;
#pragma unroll
        for (int j = 0; j < NC; ++j) { Mg[j] = 0.f; Wg[j] = 0.f; }
#pragma unroll
        for (int ii = 0; ii < 2; ++ii) {
            const int m = t + ii * NT;
            const float kv = kk[m];
            float p = 1.f;
#pragma unroll
            for (int j = 0; j < NC + 2; ++j) { M[j] += p; p *= kv; }
            const float gkv = gk[m], gvv = gv[m];
            float pg = 1.f;
#pragma unroll
            for (int j = 0; j < NC; ++j) { Mg[j] += pg; Wg[j] += gvv * pg; pg *= gkv; }
        }
#pragma unroll
        for (int j = 0; j < NC + 2; ++j) {
            float v = M[j];
            for (int o = 16; o; o >>= 1) v += __shfl_down_sync(0xffffffffu, v, o);
            if (lane == 0) red[j][wid] = v;
        }
#pragma unroll
        for (int j = 0; j < NC; ++j) {
            float v = Mg[j];
            for (int o = 16; o; o >>= 1) v += __shfl_down_sync(0xffffffffu, v, o);
            if (lane == 0) red[NC + 2 + j][wid] = v;
            float w = Wg[j];
            for (int o = 16; o; o >>= 1) w += __shfl_down_sync(0xffffffffu, w, o);
            if (lane == 0) red[2 * NC + 2 + j][wid] = w;
        }
    }

    // ---- select (half==1 blocks): warps 0-7 top-20, warps 8-15 bottom-20 ----
    if (half == 1) {
        const int sw = wid & 7;
        const bool isBot = (wid >= 8);
        unsigned long long key[4];
#pragma unroll
        for (int i = 0; i < 4; ++i) {
            const int m = sw * 128 + i * 32 + lane;
            unsigned f = ford(kk[m]);
            if (isBot) f = ~f;
            key[i] = ((unsigned long long)f << 32) | (unsigned)(1023 - m);
        }
        unsigned long long* cand = isBot ? candB : candT;
        for (int it = 0; it < 20; ++it) {
            unsigned long long best = key[0]; int bi = 0;
#pragma unroll
            for (int i = 1; i < 4; ++i) if (key[i] > best) { best = key[i]; bi = i; }
            unsigned long long wbest = best;
#pragma unroll
            for (int o = 16; o; o >>= 1) {
                unsigned long long oth = __shfl_xor_sync(0xffffffffu, wbest, o);
                if (oth > wbest) wbest = oth;
            }
            if (best == wbest) key[bi] = 0ull;
            if (lane == 0) cand[sw * 20 + it] = wbest;
        }
    }
    __syncthreads();

    // warp 1 sums moments; warps 0 and 8 merge 160 candidates each
    if (wid == 1) {
        float s = 0.f;
#pragma unroll
        for (int w = 0; w < 16; ++w) s += red[lane][w];
        Rall[lane] = s;
    }
    if (half == 1 && (wid == 0 || wid == 8)) {
        const bool isBot = (wid == 8);
        const unsigned long long* cand = isBot ? candB : candT;
        unsigned long long k0 = cand[lane];
        unsigned long long k1 = cand[lane + 32];
        unsigned long long k2 = cand[lane + 64];
        unsigned long long k3 = cand[lane + 96];
        unsigned long long k4 = cand[lane + 128];
        for (int it = 0; it < 20; ++it) {
            unsigned long long best = k0; int bi = 0;
            if (k1 > best) { best = k1; bi = 1; }
            if (k2 > best) { best = k2; bi = 2; }
            if (k3 > best) { best = k3; bi = 3; }
            if (k4 > best) { best = k4; bi = 4; }
            unsigned long long wbest = best;
#pragma unroll
            for (int o = 16; o; o >>= 1) {
                unsigned long long oth = __shfl_xor_sync(0xffffffffu, wbest, o);
                if (oth > wbest) wbest = oth;
            }
            if (best == wbest) {
                if (bi == 0) k0 = 0ull; else if (bi == 1) k1 = 0ull;
                else if (bi == 2) k2 = 0ull; else if (bi == 3) k3 = 0ull; else k4 = 0ull;
            }
            if (lane == 0) {
                const int m = 1023 - (int)(unsigned)wbest;
                if (!isBot) { tkS[it] = kk[m]; tvS[it] = vv[m]; }
                else        { bkS[it] = kk[m]; bvS[it] = vv[m]; }
            }
        }
    }
    __syncthreads();

    if (t < NC) {
        const float f = c_invf[t];
        coefD[t]  = Rall[t] * f;
        coefS1[t] = Rall[t + 1] * f;
        coefDg[t] = Rall[NC + 2 + t] * f;
        coefSv[t] = Rall[2 * NC + 2 + t] * f;
        if (half == 0) g_hdD[h][t] = coefD[t];
    }
    if (half == 1) {
        if (t < KMAX) {
            g_tk[h][t] = tkS[t]; g_tv[h][t] = tvS[t];
            g_bk[h][t] = bkS[t]; g_bv[h][t] = bvS[t];
        }
        if (t == 0) {
            float s = 0.f;
            for (int i = 0; i < KMAX; ++i) { s += vv[i]; g_vpre[h][i] = s; }
        }
    }
    __syncthreads();

    // ---- entropy + global attention (512 rows, 1/thread) ----
    {
        const int n = half * 512 + t;
        const float a = qs[t] * SCALE;
        const float D = horner10(coefD, a);
        const float S1 = horner10(coefS1, a);
        float ent = __logf(D) - a * S1 / D;
        const float ag = gqs[t] * SCALE;
        g_gx[n * 64 + h] = horner10(coefSv, ag) / horner10(coefDg, ag);
        for (int o = 16; o; o >>= 1) ent += __shfl_down_sync(0xffffffffu, ent, o);
        if (lane == 0) red[0][wid] = ent;
    }
    __syncthreads();
    if (t == 0) {
        float s = 0.f;
#pragma unroll
        for (int w = 0; w < 16; ++w) s += red[0][w];
        g_entpart[b] = s;
    }

    gridbar(1);

    // ================= Phase C: km, local attn, fuse, proj =================
    float* cDs = kk;          // [64][NC]
    float* cLp = vv;          // [64][NC]
    float* cLn = gk;          // [64][NC]
    float* lxS = gv;          // [0..511]
    float* gxS = gv + 512;    // [512..1023]
    float* ttS = qs;          // [0..511]

    // km: warp 0 fixed-order (identical in every block)
    if (wid == 0) {
        float s = 0.f;
#pragma unroll
        for (int i = 0; i < 4; ++i) s += g_entpart[lane * 4 + i];
        for (int o = 16; o; o >>= 1) s += __shfl_down_sync(0xffffffffu, s, o);
        if (lane == 0) {
            const float em = s * (1.f / (float)(NH * NN));
            int km = 5 + (int)rintf(15.f * em);
            if (km < 5) km = 5;
            if (km > 20) km = 20;
            km_s = km;
        }
    }
    // coalesced loads while warp 0 reduces
    for (int i = t; i < 64 * NC; i += NT) cDs[i] = (&g_hdD[0][0])[i];
    gxS[t] = g_gx[n0 * 64 + t];
    {   // importance partials: 8 segments of 16 blocks
        const int c = t & 63, seg = t >> 6;
        float p = 0.f;
#pragma unroll 16
        for (int i = 0; i < 16; ++i) p += g_xpart[seg * 16 + i][c];
        spart[seg][c] = p;
    }
    __syncthreads();
    const int km = km_s;

    // local-numerator Taylor coefs per (head, sign): threads 0..127
    if (t < 128) {
        const int hh = t & 63;
        const bool isBot = (t >= 64);
        const float* kp = isBot ? g_bk[hh] : g_tk[hh];
        const float* vp = isBot ? g_bv[hh] : g_tv[hh];
        float cl[NC];
#pragma unroll
        for (int j = 0; j < NC; ++j) cl[j] = 0.f;
        for (int i = 0; i < km; ++i) {
            const float kv = kp[i];
            float p = vp[i];
#pragma unroll
            for (int j = 0; j < NC; ++j) { cl[j] += p; p *= kv; }
        }
        float* dst = (isBot ? cLn : cLp) + hh * NC;
#pragma unroll
        for (int j = 0; j < NC; ++j) dst[j] = cl[j] * c_invf[j];
    }
    if (t >= 448) {   // warp 14: importance combine
        const int c = t - 448;
        if (c < 64) {
            float cs = 0.f;
#pragma unroll
            for (int s8 = 0; s8 < 8; ++s8) cs += spart[s8][c];
            sred[c] = cs * (1.f / (float)NN) * hg_w[c];
        }
    }
    __syncthreads();
    if (t == 0) {
        float l = hg_b[0];
#pragma unroll
        for (int j = 0; j < 64; ++j) l += sred[j];
        const float imp = 1.f / (1.f + expf(-l));
        early_s = (imp < 0.1f) ? 1 : 0;
    }

    // local attention for this block's 8 rows x 64 heads (1/thread)
    {
        const int hh = t & 63, r = t >> 6;
        const float a = qsS[r * 64 + hh] * SCALE;
        const float D = horner10(cDs + hh * NC, a);
        float num;
        if (a > 0.f)      num = horner10(cLp + hh * NC, a);
        else if (a < 0.f) num = horner10(cLn + hh * NC, a);
        else              num = g_vpre[hh][km - 1];
        lxS[r * 64 + hh] = num / D;
    }
    __syncthreads();

    const int c = t & 63, r = t >> 6;
    {
        float f = fus_b[c];
#pragma unroll 16
        for (int j = 0; j < 64; ++j) f = fmaf(lxS[r * 64 + j], fus_w[j * 64 + c], f);
#pragma unroll 16
        for (int j = 0; j < 64; ++j) f = fmaf(gxS[r * 64 + j], fus_w[(64 + j) * 64 + c], f);
        ttS[r * 64 + c] = xmS[r * 64 + c] + f;
    }
    __syncthreads();
    const int early = early_s;
    {
        float o = proj_b[c];
#pragma unroll 16
        for (int j = 0; j < 64; ++j) o = fmaf(ttS[r * 64 + j], proj_w[j * 64 + c], o);
        out[(n0 + r) * 64 + c] = early ? xs[r * 64 + c] : o;
    }
}

extern "C" void kernel_launch(void* const* d_in, const int* in_sizes, int n_in,
                              void* d_out, int out_size) {
    const float* x      = (const float*)d_in[0];
    const float* qkv_w  = (const float*)d_in[1];
    const float* qkv_b  = (const float*)d_in[2];
    const float* gqkv_w = (const float*)d_in[3];
    const float* gqkv_b = (const float*)d_in[4];
    const float* cg_w   = (const float*)d_in[5];
    const float* cg_b   = (const float*)d_in[6];
    const float* hg_w   = (const float*)d_in[7];
    const float* hg_b   = (const float*)d_in[8];
    const float* fus_w  = (const float*)d_in[9];
    const float* fus_b  = (const float*)d_in[10];
    const float* proj_w = (const float*)d_in[11];
    const float* proj_b = (const float*)d_in[12];
    float* out = (float*)d_out;

    fused_kernel<<<NB, NT>>>(x, qkv_w, qkv_b, gqkv_w, gqkv_b, cg_w, cg_b,
                             hg_w, hg_b, fus_w, fus_b, proj_w, proj_b, out);
}

// round 7
// speedup vs baseline: 2.0549x; 1.0096x over previous
#include <cuda_runtime.h>
#include <math.h>

#define NN 1024
#define NH 64
#define NC 10             // Taylor terms (degree 9)
#define SCALE 0.125f
#define KMAX 20
#define NB 128
#define NT 512
#define RPB 8
#define GATE_THR (-2.1972245773362196f)   // logit(0.1)

// -------- device scratch --------
__device__ float g_q[NH][NN], g_k[NH][NN], g_v[NH][NN];
__device__ float g_gq[NH][NN], g_gk[NH][NN], g_gv[NH][NN];
__device__ float g_xpart[NB][64];
__device__ float g_entpart[NB];
__device__ float g_gx[NN * 64];
__device__ float g_hdD[NH][NC];
__device__ float g_tkT[KMAX][NH], g_tvT[KMAX][NH];
__device__ float g_bkT[KMAX][NH], g_bvT[KMAX][NH];
__device__ float g_vpreT[KMAX][NH];
__device__ int   g_earlyflag;
__device__ unsigned g_barcnt[4];      // zero-init; monotonic across replays

__constant__ float c_invf[NC] = {
    1.0f, 1.0f, 0.5f, 1.66666672e-01f, 4.16666679e-02f, 8.33333377e-03f,
    1.38888892e-03f, 1.98412701e-04f, 2.48015876e-05f, 2.75573188e-06f };

__device__ __forceinline__ unsigned ford(float f) {
    unsigned u = __float_as_uint(f);
    return (u & 0x80000000u) ? ~u : (u | 0x80000000u);
}

__device__ __forceinline__ float horner10(const float* c, float a) {
    float r = c[NC - 1];
#pragma unroll
    for (int j = NC - 2; j >= 0; --j) r = fmaf(r, a, c[j]);
    return r;
}

// grid barrier: release-atomic + acquire-load spin (no full fence, no nanosleep)
__device__ __forceinline__ void gridbar(int idx) {
    __syncthreads();
    if (threadIdx.x == 0) {
        unsigned* addr = &g_barcnt[idx];
        unsigned my;
        asm volatile("atom.release.gpu.global.add.u32 %0, [%1], 1;"
                     : "=r"(my) : "l"(addr) : "memory");
        const unsigned target = (my / (unsigned)NB + 1u) * (unsigned)NB;
        unsigned cur;
        do {
            asm volatile("ld.acquire.gpu.global.u32 %0, [%1];"
                         : "=r"(cur) : "l"(addr) : "memory");
        } while (cur < target);
    }
    __syncthreads();
}

__global__ __launch_bounds__(NT, 1)
void fused_kernel(const float* __restrict__ x,
                  const float* __restrict__ qkv_w,  const float* __restrict__ qkv_b,
                  const float* __restrict__ gqkv_w, const float* __restrict__ gqkv_b,
                  const float* __restrict__ cg_w,   const float* __restrict__ cg_b,
                  const float* __restrict__ hg_w,   const float* __restrict__ hg_b,
                  const float* __restrict__ fus_w,  const float* __restrict__ fus_b,
                  const float* __restrict__ proj_w, const float* __restrict__ proj_b,
                  float* __restrict__ out) {
    __shared__ float xs[RPB * 64];     // persists A->C
    __shared__ float xmS[RPB * 64];    // persists A->C
    __shared__ float qsS[RPB * 64];    // q of this block's rows (persists A->C)
    __shared__ float kk[NN], vv[NN], gk[NN], gv[NN];   // B; reused as scratch in C
    __shared__ float qs[512], gqs[512];                // B; qs reused as ttS in C
    __shared__ unsigned long long candT[160], candB[160];
    __shared__ float red[32][16];
    __shared__ float Rall[32];
    __shared__ float coefD[NC], coefS1[NC], coefDg[NC], coefSv[NC];
    __shared__ float tkS[KMAX], tvS[KMAX], bkS[KMAX], bvS[KMAX];
    __shared__ float sred[64];
    __shared__ int   km_s, early_s;

    const int b = blockIdx.x;
    const int t = threadIdx.x;
    const int lane = t & 31, wid = t >> 5;
    const int n0 = b * RPB;

    // ================= Phase A: gate + qkv/gqkv GEMMs (8 rows) =================
    xs[t] = x[n0 * 64 + t];            // RPB*64 == NT
    __syncthreads();

    if (t < 64) {
        float s = 0.f;
#pragma unroll
        for (int r = 0; r < RPB; ++r) s += xs[r * 64 + t];
        g_xpart[b][t] = s;
    }
    {   // content gate: 512 outputs, 1 per thread
        const int c = t & 63, r = t >> 6;
        float l = cg_b[c];
#pragma unroll
        for (int j = 0; j < 64; ++j) l = fmaf(xs[r * 64 + j], cg_w[j * 64 + c], l);
        xmS[r * 64 + c] = (l > (float)GATE_THR) ? xs[r * 64 + c] : 0.f;
    }
    __syncthreads();

    // qkv+gqkv: threads 0..383, one column each, 8-row register tile
    if (t < 384) {
        const bool isg = (t >= 192);
        const int c = isg ? t - 192 : t;
        const float* wp = isg ? gqkv_w : qkv_w;
        float acc[RPB];
        const float bias = isg ? gqkv_b[c] : qkv_b[c];
#pragma unroll
        for (int r = 0; r < RPB; ++r) acc[r] = bias;
#pragma unroll 16
        for (int j = 0; j < 64; ++j) {
            const float w = wp[j * 192 + c];
#pragma unroll
            for (int r = 0; r < RPB; ++r) acc[r] = fmaf(xmS[r * 64 + j], w, acc[r]);
        }
        const int h = c & 63, part = c >> 6;
        if (!isg && part == 0) {
#pragma unroll
            for (int r = 0; r < RPB; ++r) qsS[r * 64 + h] = acc[r];
        }
        float* dst = isg ? (part == 0 ? g_gq[h] : part == 1 ? g_gk[h] : g_gv[h])
                         : (part == 0 ? g_q[h]  : part == 1 ? g_k[h]  : g_v[h]);
        *(float4*)(dst + n0)     = make_float4(acc[0], acc[1], acc[2], acc[3]);
        *(float4*)(dst + n0 + 4) = make_float4(acc[4], acc[5], acc[6], acc[7]);
    }

    gridbar(0);

    // ================= Phase B: head stats + entropy + global attn =================
    const int h = b >> 1, half = b & 1;
#pragma unroll
    for (int ii = 0; ii < 2; ++ii) {
        const int i = t + ii * NT;
        kk[i] = g_k[h][i];
        gk[i] = g_gk[h][i]; gv[i] = g_gv[h][i];
    }
    if (half == 1) {
#pragma unroll
        for (int ii = 0; ii < 2; ++ii) { const int i = t + ii * NT; vv[i] = g_v[h][i]; }
    }
    qs[t]  = g_q[h][half * 512 + t];
    gqs[t] = g_gq[h][half * 512 + t];
    __syncthreads();

    // ---- moments (2 elements per thread) ----
    {
        float M[NC + 2], Mg[NC], Wg[NC];
#pragma unroll
        for (int j = 0; j < NC + 2; ++j) M[j] = 0.f;
#pragma unroll
        for (int j = 0; j < NC; ++j) { Mg[j] = 0.f; Wg[j] = 0.f; }
#pragma unroll
        for (int ii = 0; ii < 2; ++ii) {
            const int m = t + ii * NT;
            const float kv = kk[m];
            float p = 1.f;
#pragma unroll
            for (int j = 0; j < NC + 2; ++j) { M[j] += p; p *= kv; }
            const float gkv = gk[m], gvv = gv[m];
            float pg = 1.f;
#pragma unroll
            for (int j = 0; j < NC; ++j) { Mg[j] += pg; Wg[j] += gvv * pg; pg *= gkv; }
        }
#pragma unroll
        for (int j = 0; j < NC + 2; ++j) {
            float v = M[j];
            for (int o = 16; o; o >>= 1) v += __shfl_down_sync(0xffffffffu, v, o);
            if (lane == 0) red[j][wid] = v;
        }
#pragma unroll
        for (int j = 0; j < NC; ++j) {
            float v = Mg[j];
            for (int o = 16; o; o >>= 1) v += __shfl_down_sync(0xffffffffu, v, o);
            if (lane == 0) red[NC + 2 + j][wid] = v;
            float w = Wg[j];
            for (int o = 16; o; o >>= 1) w += __shfl_down_sync(0xffffffffu, w, o);
            if (lane == 0) red[2 * NC + 2 + j][wid] = w;
        }
    }

    // ---- select (half==1): warps 0-7 top-20, warps 8-15 bottom-20 ----
    if (half == 1) {
        const int sw = wid & 7;
        const bool isBot = (wid >= 8);
        unsigned long long key[4];
#pragma unroll
        for (int i = 0; i < 4; ++i) {
            const int m = sw * 128 + i * 32 + lane;
            unsigned f = ford(kk[m]);
            if (isBot) f = ~f;
            key[i] = ((unsigned long long)f << 32) | (unsigned)(1023 - m);
        }
        unsigned long long* cand = isBot ? candB : candT;
        for (int it = 0; it < 20; ++it) {
            unsigned long long best = key[0]; int bi = 0;
#pragma unroll
            for (int i = 1; i < 4; ++i) if (key[i] > best) { best = key[i]; bi = i; }
            unsigned long long wbest = best;
#pragma unroll
            for (int o = 16; o; o >>= 1) {
                unsigned long long oth = __shfl_xor_sync(0xffffffffu, wbest, o);
                if (oth > wbest) wbest = oth;
            }
            if (best == wbest) key[bi] = 0ull;
            if (lane == 0) cand[sw * 20 + it] = wbest;
        }
    } else {
        // half==0 blocks: importance partials (overlaps with other blocks' select)
        if (t < 64) {
            float cs = 0.f;
#pragma unroll 16
            for (int i = 0; i < NB; ++i) cs += g_xpart[i][t];
            sred[t] = cs * (1.f / (float)NN) * hg_w[t];
        }
    }
    __syncthreads();

    // warp 1 sums moments; warps 0 and 8 merge candidates; t==0 (half==0) early flag
    if (wid == 1) {
        float s = 0.f;
#pragma unroll
        for (int w = 0; w < 16; ++w) s += red[lane][w];
        Rall[lane] = s;
    }
    if (half == 0 && t == 0) {
        float l = hg_b[0];
#pragma unroll
        for (int j = 0; j < 64; ++j) l += sred[j];
        const float imp = 1.f / (1.f + expf(-l));
        if (b == 0) g_earlyflag = (imp < 0.1f) ? 1 : 0;
    }
    if (half == 1 && (wid == 0 || wid == 8)) {
        const bool isBot = (wid == 8);
        const unsigned long long* cand = isBot ? candB : candT;
        unsigned long long k0 = cand[lane];
        unsigned long long k1 = cand[lane + 32];
        unsigned long long k2 = cand[lane + 64];
        unsigned long long k3 = cand[lane + 96];
        unsigned long long k4 = cand[lane + 128];
        for (int it = 0; it < 20; ++it) {
            unsigned long long best = k0; int bi = 0;
            if (k1 > best) { best = k1; bi = 1; }
            if (k2 > best) { best = k2; bi = 2; }
            if (k3 > best) { best = k3; bi = 3; }
            if (k4 > best) { best = k4; bi = 4; }
            unsigned long long wbest = best;
#pragma unroll
            for (int o = 16; o; o >>= 1) {
                unsigned long long oth = __shfl_xor_sync(0xffffffffu, wbest, o);
                if (oth > wbest) wbest = oth;
            }
            if (best == wbest) {
                if (bi == 0) k0 = 0ull; else if (bi == 1) k1 = 0ull;
                else if (bi == 2) k2 = 0ull; else if (bi == 3) k3 = 0ull; else k4 = 0ull;
            }
            if (lane == 0) {
                const int m = 1023 - (int)(unsigned)wbest;
                if (!isBot) { tkS[it] = kk[m]; tvS[it] = vv[m]; }
                else        { bkS[it] = kk[m]; bvS[it] = vv[m]; }
            }
        }
    }
    __syncthreads();

    if (t < NC) {
        const float f = c_invf[t];
        coefD[t]  = Rall[t] * f;
        coefS1[t] = Rall[t + 1] * f;
        coefDg[t] = Rall[NC + 2 + t] * f;
        coefSv[t] = Rall[2 * NC + 2 + t] * f;
        if (half == 0) g_hdD[h][t] = coefD[t];
    }
    if (half == 1) {
        if (t < KMAX) {
            g_tkT[t][h] = tkS[t]; g_tvT[t][h] = tvS[t];
            g_bkT[t][h] = bkS[t]; g_bvT[t][h] = bvS[t];
        }
        if (t == 0) {
            float s = 0.f;
            for (int i = 0; i < KMAX; ++i) { s += vv[i]; g_vpreT[i][h] = s; }
        }
    }
    __syncthreads();

    // ---- entropy + global attention (512 rows, 1/thread) ----
    {
        const int n = half * 512 + t;
        const float a = qs[t] * SCALE;
        const float D = horner10(coefD, a);
        const float S1 = horner10(coefS1, a);
        float ent = __logf(D) - a * S1 / D;
        const float ag = gqs[t] * SCALE;
        g_gx[n * 64 + h] = horner10(coefSv, ag) / horner10(coefDg, ag);
        for (int o = 16; o; o >>= 1) ent += __shfl_down_sync(0xffffffffu, ent, o);
        if (lane == 0) red[0][wid] = ent;
    }
    __syncthreads();
    if (t == 0) {
        float s = 0.f;
#pragma unroll
        for (int w = 0; w < 16; ++w) s += red[0][w];
        g_entpart[b] = s;
    }

    gridbar(1);

    // ================= Phase C: km, local attn, fuse, proj =================
    float* cDs = kk;          // [64][NC]
    float* cLp = vv;          // [64][NC]
    float* cLn = gk;          // [64][NC]
    float* lxS = gv;          // [0..511]
    float* gxS = gv + 512;    // [512..1023]
    float* ttS = qs;          // [0..511]

    // km: warp 0 fixed-order (identical in every block)
    if (wid == 0) {
        float s = 0.f;
#pragma unroll
        for (int i = 0; i < 4; ++i) s += g_entpart[lane * 4 + i];
        for (int o = 16; o; o >>= 1) s += __shfl_down_sync(0xffffffffu, s, o);
        if (lane == 0) {
            const float em = s * (1.f / (float)(NH * NN));
            int km = 5 + (int)rintf(15.f * em);
            if (km < 5) km = 5;
            if (km > 20) km = 20;
            km_s = km;
        }
    }
    if (t == 256) early_s = g_earlyflag;
    // coalesced loads (overlapping warp 0's reduce)
    for (int i = t; i < 64 * NC; i += NT) cDs[i] = (&g_hdD[0][0])[i];
    gxS[t] = g_gx[n0 * 64 + t];
    __syncthreads();
    const int km = km_s;

    // local-numerator Taylor coefs per (head, sign): warps 4-7, coalesced loads
    if (t >= 128 && t < 256) {
        const int u = t - 128;
        const int hh = u & 63;
        const bool isBot = (u >= 64);
        float cl[NC];
#pragma unroll
        for (int j = 0; j < NC; ++j) cl[j] = 0.f;
        for (int i = 0; i < km; ++i) {
            const float kv = isBot ? g_bkT[i][hh] : g_tkT[i][hh];
            float p       = isBot ? g_bvT[i][hh] : g_tvT[i][hh];
#pragma unroll
            for (int j = 0; j < NC; ++j) { cl[j] += p; p *= kv; }
        }
        float* dst = (isBot ? cLn : cLp) + hh * NC;
#pragma unroll
        for (int j = 0; j < NC; ++j) dst[j] = cl[j] * c_invf[j];
    }
    __syncthreads();

    // local attention for this block's 8 rows x 64 heads (1/thread)
    {
        const int hh = t & 63, r = t >> 6;
        const float a = qsS[r * 64 + hh] * SCALE;
        const float D = horner10(cDs + hh * NC, a);
        float num;
        if (a > 0.f)      num = horner10(cLp + hh * NC, a);
        else if (a < 0.f) num = horner10(cLn + hh * NC, a);
        else              num = g_vpreT[km - 1][hh];
        lxS[r * 64 + hh] = num / D;
    }
    __syncthreads();

    const int c = t & 63, r = t >> 6;
    {
        float f = fus_b[c];
#pragma unroll 16
        for (int j = 0; j < 64; ++j) f = fmaf(lxS[r * 64 + j], fus_w[j * 64 + c], f);
#pragma unroll 16
        for (int j = 0; j < 64; ++j) f = fmaf(gxS[r * 64 + j], fus_w[(64 + j) * 64 + c], f);
        ttS[r * 64 + c] = xmS[r * 64 + c] + f;
    }
    __syncthreads();
    const int early = early_s;
    {
        float o = proj_b[c];
#pragma unroll 16
        for (int j = 0; j < 64; ++j) o = fmaf(ttS[r * 64 + j], proj_w[j * 64 + c], o);
        out[(n0 + r) * 64 + c] = early ? xs[r * 64 + c] : o;
    }
}

extern "C" void kernel_launch(void* const* d_in, const int* in_sizes, int n_in,
                              void* d_out, int out_size) {
    const float* x      = (const float*)d_in[0];
    const float* qkv_w  = (const float*)d_in[1];
    const float* qkv_b  = (const float*)d_in[2];
    const float* gqkv_w = (const float*)d_in[3];
    const float* gqkv_b = (const float*)d_in[4];
    const float* cg_w   = (const float*)d_in[5];
    const float* cg_b   = (const float*)d_in[6];
    const float* hg_w   = (const float*)d_in[7];
    const float* hg_b   = (const float*)d_in[8];
    const float* fus_w  = (const float*)d_in[9];
    const float* fus_b  = (const float*)d_in[10];
    const float* proj_w = (const float*)d_in[11];
    const float* proj_b = (const float*)d_in[12];
    float* out = (float*)d_out;

    fused_kernel<<<NB, NT>>>(x, qkv_w, qkv_b, gqkv_w, gqkv_b, cg_w, cg_b,
                             hg_w, hg_b, fus_w, fus_b, proj_w, proj_b, out);
}

// round 8
// speedup vs baseline: 2.5177x; 1.2252x over previous
#include <cuda_runtime.h>
#include <math.h>

#define NN 1024
#define NH 64
#define NC 8              // Taylor terms (degree 7)
#define NCP 9             // padded stride for per-head coef arrays (odd -> no bank conflicts)
#define SCALE 0.125f
#define KMAX 20
#define NB 128
#define NT 512
#define RPB 8
#define GATE_THR (-2.1972245773362196f)   // logit(0.1)

// -------- device scratch --------
__device__ float g_q[NH][NN], g_k[NH][NN], g_v[NH][NN];
__device__ float g_gq[NH][NN], g_gk[NH][NN], g_gv[NH][NN];
__device__ float g_xpart[NB][64];
__device__ float g_entpart[NB];
__device__ float g_gx[NN * 64];
__device__ float g_hdD[NH][NC];
__device__ __align__(16) float g_tkT[KMAX][NH];
__device__ __align__(16) float g_tvT[KMAX][NH];
__device__ __align__(16) float g_bkT[KMAX][NH];
__device__ __align__(16) float g_bvT[KMAX][NH];
__device__ float g_vpreT[KMAX][NH];
__device__ int   g_earlyflag;
__device__ unsigned g_barcnt[4];      // zero-init; monotonic across replays

__constant__ float c_invf[NC] = {
    1.0f, 1.0f, 0.5f, 1.66666672e-01f, 4.16666679e-02f, 8.33333377e-03f,
    1.38888892e-03f, 1.98412701e-04f };

__device__ __forceinline__ unsigned ford(float f) {
    unsigned u = __float_as_uint(f);
    return (u & 0x80000000u) ? ~u : (u | 0x80000000u);
}

__device__ __forceinline__ float horner8(const float* c, float a) {
    float r = c[NC - 1];
#pragma unroll
    for (int j = NC - 2; j >= 0; --j) r = fmaf(r, a, c[j]);
    return r;
}

// grid barrier: release-atomic + acquire-load spin
__device__ __forceinline__ void gridbar(int idx) {
    __syncthreads();
    if (threadIdx.x == 0) {
        unsigned* addr = &g_barcnt[idx];
        unsigned my;
        asm volatile("atom.release.gpu.global.add.u32 %0, [%1], 1;"
                     : "=r"(my) : "l"(addr) : "memory");
        const unsigned target = (my / (unsigned)NB + 1u) * (unsigned)NB;
        unsigned cur;
        do {
            asm volatile("ld.acquire.gpu.global.u32 %0, [%1];"
                         : "=r"(cur) : "l"(addr) : "memory");
        } while (cur < target);
    }
    __syncthreads();
}

__global__ __launch_bounds__(NT, 1)
void fused_kernel(const float* __restrict__ x,
                  const float* __restrict__ qkv_w,  const float* __restrict__ qkv_b,
                  const float* __restrict__ gqkv_w, const float* __restrict__ gqkv_b,
                  const float* __restrict__ cg_w,   const float* __restrict__ cg_b,
                  const float* __restrict__ hg_w,   const float* __restrict__ hg_b,
                  const float* __restrict__ fus_w,  const float* __restrict__ fus_b,
                  const float* __restrict__ proj_w, const float* __restrict__ proj_b,
                  float* __restrict__ out) {
    __shared__ __align__(16) float xs[RPB * 64];     // persists A->C
    __shared__ __align__(16) float xmS[RPB * 64];    // persists A->C
    __shared__ __align__(16) float qsS[RPB * 64];    // persists A->C
    __shared__ __align__(16) float kk[NN], vv[NN], gk[NN], gv[NN];
    __shared__ __align__(16) float qs[512], gqs[512];
    __shared__ __align__(16) float stg[4 * KMAX * 64];   // phase C: staged top/bot k/v
    __shared__ unsigned long long candT[160], candB[160];
    __shared__ float red[25][16];
    __shared__ float Rall[25];
    __shared__ float coefD[NC], coefS1[NC], coefDg[NC], coefSv[NC];
    __shared__ float tkS[KMAX], tvS[KMAX], bkS[KMAX], bvS[KMAX];
    __shared__ float sred[64];
    __shared__ int   km_s, early_s;

    const int b = blockIdx.x;
    const int t = threadIdx.x;
    const int lane = t & 31, wid = t >> 5;
    const int n0 = b * RPB;

    // ================= Phase A: gate + qkv/gqkv GEMMs (8 rows) =================
    xs[t] = x[n0 * 64 + t];            // RPB*64 == NT
    __syncthreads();

    if (t < 64) {
        float s = 0.f;
#pragma unroll
        for (int r = 0; r < RPB; ++r) s += xs[r * 64 + t];
        g_xpart[b][t] = s;
    }
    {   // content gate: 512 outputs, 1 per thread (float4 LDS)
        const int c = t & 63, r = t >> 6;
        const float4* xs4 = (const float4*)xs;
        float l = cg_b[c];
#pragma unroll
        for (int j4 = 0; j4 < 16; ++j4) {
            const float w0 = cg_w[(j4 * 4 + 0) * 64 + c];
            const float w1 = cg_w[(j4 * 4 + 1) * 64 + c];
            const float w2 = cg_w[(j4 * 4 + 2) * 64 + c];
            const float w3 = cg_w[(j4 * 4 + 3) * 64 + c];
            const float4 xv = xs4[r * 16 + j4];
            l = fmaf(xv.x, w0, l); l = fmaf(xv.y, w1, l);
            l = fmaf(xv.z, w2, l); l = fmaf(xv.w, w3, l);
        }
        xmS[r * 64 + c] = (l > (float)GATE_THR) ? xs[r * 64 + c] : 0.f;
    }
    __syncthreads();

    // qkv+gqkv: threads 0..383, one column each, 8-row tile, float4 LDS
    if (t < 384) {
        const bool isg = (t >= 192);
        const int c = isg ? t - 192 : t;
        const float* wp = isg ? gqkv_w : qkv_w;
        const float4* xm4 = (const float4*)xmS;
        float acc[RPB];
        const float bias = isg ? gqkv_b[c] : qkv_b[c];
#pragma unroll
        for (int r = 0; r < RPB; ++r) acc[r] = bias;
#pragma unroll
        for (int j4 = 0; j4 < 16; ++j4) {
            const float w0 = wp[(j4 * 4 + 0) * 192 + c];
            const float w1 = wp[(j4 * 4 + 1) * 192 + c];
            const float w2 = wp[(j4 * 4 + 2) * 192 + c];
            const float w3 = wp[(j4 * 4 + 3) * 192 + c];
#pragma unroll
            for (int r = 0; r < RPB; ++r) {
                const float4 xv = xm4[r * 16 + j4];
                acc[r] = fmaf(xv.x, w0, acc[r]);
                acc[r] = fmaf(xv.y, w1, acc[r]);
                acc[r] = fmaf(xv.z, w2, acc[r]);
                acc[r] = fmaf(xv.w, w3, acc[r]);
            }
        }
        const int h = c & 63, part = c >> 6;
        if (!isg && part == 0) {
#pragma unroll
            for (int r = 0; r < RPB; ++r) qsS[r * 64 + h] = acc[r];
        }
        float* dst = isg ? (part == 0 ? g_gq[h] : part == 1 ? g_gk[h] : g_gv[h])
                         : (part == 0 ? g_q[h]  : part == 1 ? g_k[h]  : g_v[h]);
        *(float4*)(dst + n0)     = make_float4(acc[0], acc[1], acc[2], acc[3]);
        *(float4*)(dst + n0 + 4) = make_float4(acc[4], acc[5], acc[6], acc[7]);
    }

    gridbar(0);

    // ================= Phase B: head stats + entropy + global attn =================
    const int h = b >> 1, half = b & 1;
#pragma unroll
    for (int ii = 0; ii < 2; ++ii) {
        const int i = t + ii * NT;
        kk[i] = g_k[h][i];
        gk[i] = g_gk[h][i]; gv[i] = g_gv[h][i];
    }
    if (half == 1) {
#pragma unroll
        for (int ii = 0; ii < 2; ++ii) { const int i = t + ii * NT; vv[i] = g_v[h][i]; }
    }
    qs[t]  = g_q[h][half * 512 + t];
    gqs[t] = g_gq[h][half * 512 + t];
    __syncthreads();

    // ---- moments (2 elements per thread): M0..M8, Mg0..7, Wg0..7 ----
    {
        float M[NC + 1], Mg[NC], Wg[NC];
#pragma unroll
        for (int j = 0; j < NC + 1; ++j) M[j] = 0.f;
#pragma unroll
        for (int j = 0; j < NC; ++j) { Mg[j] = 0.f; Wg[j] = 0.f; }
#pragma unroll
        for (int ii = 0; ii < 2; ++ii) {
            const int m = t + ii * NT;
            const float kv = kk[m];
            float p = 1.f;
#pragma unroll
            for (int j = 0; j < NC + 1; ++j) { M[j] += p; p *= kv; }
            const float gkv = gk[m], gvv = gv[m];
            float pg = 1.f;
#pragma unroll
            for (int j = 0; j < NC; ++j) { Mg[j] += pg; Wg[j] += gvv * pg; pg *= gkv; }
        }
#pragma unroll
        for (int j = 0; j < NC + 1; ++j) {
            float v = M[j];
            for (int o = 16; o; o >>= 1) v += __shfl_down_sync(0xffffffffu, v, o);
            if (lane == 0) red[j][wid] = v;
        }
#pragma unroll
        for (int j = 0; j < NC; ++j) {
            float v = Mg[j];
            for (int o = 16; o; o >>= 1) v += __shfl_down_sync(0xffffffffu, v, o);
            if (lane == 0) red[NC + 1 + j][wid] = v;
            float w = Wg[j];
            for (int o = 16; o; o >>= 1) w += __shfl_down_sync(0xffffffffu, w, o);
            if (lane == 0) red[2 * NC + 1 + j][wid] = w;
        }
    }

    // ---- select (half==1): warps 0-7 top-20, warps 8-15 bottom-20 (REDUX) ----
    if (half == 1) {
        const int sw = wid & 7;
        const bool isBot = (wid >= 8);
        unsigned long long key[4];
#pragma unroll
        for (int i = 0; i < 4; ++i) {
            const int m = sw * 128 + i * 32 + lane;
            unsigned f = ford(kk[m]);
            if (isBot) f = ~f;
            key[i] = ((unsigned long long)f << 32) | (unsigned)(1023 - m);
        }
        unsigned long long* cand = isBot ? candB : candT;
        for (int it = 0; it < 20; ++it) {
            unsigned long long best = key[0]; int bi = 0;
#pragma unroll
            for (int i = 1; i < 4; ++i) if (key[i] > best) { best = key[i]; bi = i; }
            const unsigned bh = (unsigned)(best >> 32);
            const unsigned bl = (unsigned)best;
            const unsigned wbh = __reduce_max_sync(0xffffffffu, bh);
            const unsigned wbl = __reduce_max_sync(0xffffffffu, (bh == wbh) ? bl : 0u);
            if (bh == wbh && bl == wbl) key[bi] = 0ull;
            if (lane == 0) cand[sw * 20 + it] = ((unsigned long long)wbh << 32) | wbl;
        }
    } else {
        if (t < 64) {   // importance partials
            float cs = 0.f;
#pragma unroll 16
            for (int i = 0; i < NB; ++i) cs += g_xpart[i][t];
            sred[t] = cs * (1.f / (float)NN) * hg_w[t];
        }
    }
    __syncthreads();

    // warp 1 sums moments; warps 0/8 merge candidates; early flag on block 0
    if (wid == 1 && lane < 25) {
        float s = 0.f;
#pragma unroll
        for (int w = 0; w < 16; ++w) s += red[lane][w];
        Rall[lane] = s;
    }
    if (half == 0 && t == 0) {
        float l = hg_b[0];
#pragma unroll
        for (int j = 0; j < 64; ++j) l += sred[j];
        const float imp = 1.f / (1.f + expf(-l));
        if (b == 0) g_earlyflag = (imp < 0.1f) ? 1 : 0;
    }
    if (half == 1 && (wid == 0 || wid == 8)) {
        const bool isBot = (wid == 8);
        const unsigned long long* cand = isBot ? candB : candT;
        unsigned long long k0 = cand[lane];
        unsigned long long k1 = cand[lane + 32];
        unsigned long long k2 = cand[lane + 64];
        unsigned long long k3 = cand[lane + 96];
        unsigned long long k4 = cand[lane + 128];
        for (int it = 0; it < 20; ++it) {
            unsigned long long best = k0; int bi = 0;
            if (k1 > best) { best = k1; bi = 1; }
            if (k2 > best) { best = k2; bi = 2; }
            if (k3 > best) { best = k3; bi = 3; }
            if (k4 > best) { best = k4; bi = 4; }
            const unsigned bh = (unsigned)(best >> 32);
            const unsigned bl = (unsigned)best;
            const unsigned wbh = __reduce_max_sync(0xffffffffu, bh);
            const unsigned wbl = __reduce_max_sync(0xffffffffu, (bh == wbh) ? bl : 0u);
            if (bh == wbh && bl == wbl) {
                if (bi == 0) k0 = 0ull; else if (bi == 1) k1 = 0ull;
                else if (bi == 2) k2 = 0ull; else if (bi == 3) k3 = 0ull; else k4 = 0ull;
            }
            if (lane == 0) {
                const int m = 1023 - (int)wbl;
                if (!isBot) { tkS[it] = kk[m]; tvS[it] = vv[m]; }
                else        { bkS[it] = kk[m]; bvS[it] = vv[m]; }
            }
        }
    }
    __syncthreads();

    if (t < NC) {
        const float f = c_invf[t];
        coefD[t]  = Rall[t] * f;
        coefS1[t] = Rall[t + 1] * f;
        coefDg[t] = Rall[NC + 1 + t] * f;
        coefSv[t] = Rall[2 * NC + 1 + t] * f;
        if (half == 0) g_hdD[h][t] = coefD[t];
    }
    if (half == 1) {
        if (t < KMAX) {
            g_tkT[t][h] = tkS[t]; g_tvT[t][h] = tvS[t];
            g_bkT[t][h] = bkS[t]; g_bvT[t][h] = bvS[t];
        }
        if (t == 0) {
            float s = 0.f;
            for (int i = 0; i < KMAX; ++i) { s += vv[i]; g_vpreT[i][h] = s; }
        }
    }
    __syncthreads();

    // ---- entropy + global attention (512 rows, 1/thread) ----
    {
        const int n = half * 512 + t;
        const float a = qs[t] * SCALE;
        const float D = horner8(coefD, a);
        const float S1 = horner8(coefS1, a);
        float ent = __logf(D) - a * S1 / D;
        const float ag = gqs[t] * SCALE;
        g_gx[n * 64 + h] = horner8(coefSv, ag) / horner8(coefDg, ag);
        for (int o = 16; o; o >>= 1) ent += __shfl_down_sync(0xffffffffu, ent, o);
        if (lane == 0) red[0][wid] = ent;
    }
    __syncthreads();
    if (t == 0) {
        float s = 0.f;
#pragma unroll
        for (int w = 0; w < 16; ++w) s += red[0][w];
        g_entpart[b] = s;
    }

    gridbar(1);

    // ================= Phase C: km, local attn, fuse, proj =================
    float* cDs = kk;          // [64][NCP]
    float* cLp = vv;          // [64][NCP]
    float* cLn = gk;          // [64][NCP]
    float* lxS = gv;          // [0..511]
    float* gxS = gv + 512;    // [512..1023]
    float* ttS = qs;          // [0..511]

    // km: warp 0 fixed-order (identical in every block)
    if (wid == 0) {
        float s = 0.f;
#pragma unroll
        for (int i = 0; i < 4; ++i) s += g_entpart[lane * 4 + i];
        for (int o = 16; o; o >>= 1) s += __shfl_down_sync(0xffffffffu, s, o);
        if (lane == 0) {
            const float em = s * (1.f / (float)(NH * NN));
            int km = 5 + (int)rintf(15.f * em);
            if (km < 5) km = 5;
            if (km > 20) km = 20;
            km_s = km;
        }
    }
    if (t == 256) early_s = g_earlyflag;
    // staged loads (overlap warp 0's reduce): top/bot k/v, denominator coefs, gx
    if (t < 320) {
#pragma unroll
        for (int a4 = 0; a4 < 4; ++a4) {
            const float* src = (a4 == 0) ? &g_tkT[0][0] : (a4 == 1) ? &g_tvT[0][0]
                             : (a4 == 2) ? &g_bkT[0][0] : &g_bvT[0][0];
            ((float4*)(stg + a4 * KMAX * 64))[t] = ((const float4*)src)[t];
        }
    }
    {   // g_hdD [64][NC] -> cDs padded [64][NCP]
        const int hh = t >> 3, j = t & 7;
        cDs[hh * NCP + j] = (&g_hdD[0][0])[t];
    }
    gxS[t] = g_gx[n0 * 64 + t];
    __syncthreads();
    const int km = km_s;

    // local-numerator Taylor coefs per (head, sign): threads 128..255
    if (t >= 128 && t < 256) {
        const int u = t - 128;
        const int hh = u & 63;
        const bool isBot = (u >= 64);
        const float* kp = stg + (isBot ? 2 : 0) * KMAX * 64;
        const float* vp = stg + (isBot ? 3 : 1) * KMAX * 64;
        float cl[NC];
#pragma unroll
        for (int j = 0; j < NC; ++j) cl[j] = 0.f;
        for (int i = 0; i < km; ++i) {
            const float kv = kp[i * 64 + hh];
            float p = vp[i * 64 + hh];
#pragma unroll
            for (int j = 0; j < NC; ++j) { cl[j] += p; p *= kv; }
        }
        float* dst = (isBot ? cLn : cLp) + hh * NCP;
#pragma unroll
        for (int j = 0; j < NC; ++j) dst[j] = cl[j] * c_invf[j];
    }
    __syncthreads();

    // local attention for this block's 8 rows x 64 heads (1/thread)
    {
        const int hh = t & 63, r = t >> 6;
        const float a = qsS[r * 64 + hh] * SCALE;
        const float D = horner8(cDs + hh * NCP, a);
        float num;
        if (a > 0.f)      num = horner8(cLp + hh * NCP, a);
        else if (a < 0.f) num = horner8(cLn + hh * NCP, a);
        else              num = g_vpreT[km - 1][hh];
        lxS[r * 64 + hh] = num / D;
    }
    __syncthreads();

    const int c = t & 63, r = t >> 6;
    {
        const float4* lx4 = (const float4*)lxS;
        const float4* gx4 = (const float4*)gxS;
        float f = fus_b[c];
#pragma unroll
        for (int j4 = 0; j4 < 16; ++j4) {
            const float w0 = fus_w[(j4 * 4 + 0) * 64 + c];
            const float w1 = fus_w[(j4 * 4 + 1) * 64 + c];
            const float w2 = fus_w[(j4 * 4 + 2) * 64 + c];
            const float w3 = fus_w[(j4 * 4 + 3) * 64 + c];
            const float4 xv = lx4[r * 16 + j4];
            f = fmaf(xv.x, w0, f); f = fmaf(xv.y, w1, f);
            f = fmaf(xv.z, w2, f); f = fmaf(xv.w, w3, f);
        }
#pragma unroll
        for (int j4 = 0; j4 < 16; ++j4) {
            const float w0 = fus_w[(64 + j4 * 4 + 0) * 64 + c];
            const float w1 = fus_w[(64 + j4 * 4 + 1) * 64 + c];
            const float w2 = fus_w[(64 + j4 * 4 + 2) * 64 + c];
            const float w3 = fus_w[(64 + j4 * 4 + 3) * 64 + c];
            const float4 xv = gx4[r * 16 + j4];
            f = fmaf(xv.x, w0, f); f = fmaf(xv.y, w1, f);
            f = fmaf(xv.z, w2, f); f = fmaf(xv.w, w3, f);
        }
        ttS[r * 64 + c] = xmS[r * 64 + c] + f;
    }
    __syncthreads();
    const int early = early_s;
    {
        const float4* tt4 = (const float4*)ttS;
        float o = proj_b[c];
#pragma unroll
        for (int j4 = 0; j4 < 16; ++j4) {
            const float w0 = proj_w[(j4 * 4 + 0) * 64 + c];
            const float w1 = proj_w[(j4 * 4 + 1) * 64 + c];
            const float w2 = proj_w[(j4 * 4 + 2) * 64 + c];
            const float w3 = proj_w[(j4 * 4 + 3) * 64 + c];
            const float4 xv = tt4[r * 16 + j4];
            o = fmaf(xv.x, w0, o); o = fmaf(xv.y, w1, o);
            o = fmaf(xv.z, w2, o); o = fmaf(xv.w, w3, o);
        }
        out[(n0 + r) * 64 + c] = early ? xs[r * 64 + c] : o;
    }
}

extern "C" void kernel_launch(void* const* d_in, const int* in_sizes, int n_in,
                              void* d_out, int out_size) {
    const float* x      = (const float*)d_in[0];
    const float* qkv_w  = (const float*)d_in[1];
    const float* qkv_b  = (const float*)d_in[2];
    const float* gqkv_w = (const float*)d_in[3];
    const float* gqkv_b = (const float*)d_in[4];
    const float* cg_w   = (const float*)d_in[5];
    const float* cg_b   = (const float*)d_in[6];
    const float* hg_w   = (const float*)d_in[7];
    const float* hg_b   = (const float*)d_in[8];
    const float* fus_w  = (const float*)d_in[9];
    const float* fus_b  = (const float*)d_in[10];
    const float* proj_w = (const float*)d_in[11];
    const float* proj_b = (const float*)d_in[12];
    float* out = (float*)d_out;

    fused_kernel<<<NB, NT>>>(x, qkv_w, qkv_b, gqkv_w, gqkv_b, cg_w, cg_b,
                             hg_w, hg_b, fus_w, fus_b, proj_w, proj_b, out);
}

// round 9
// speedup vs baseline: 2.5207x; 1.0012x over previous
#include <cuda_runtime.h>
#include <math.h>

#define NN 1024
#define NH 64
#define NC 8              // Taylor terms (degree 7)
#define NCP 9             // padded stride (odd -> conflict-free)
#define SCALE 0.125f
#define KMAX 20
#define NB 128
#define NT 512
#define RPB 8
#define GATE_THR (-2.1972245773362196f)   // logit(0.1)

// -------- device scratch --------
__device__ float g_q[NH][NN], g_k[NH][NN], g_v[NH][NN];
__device__ float g_gk[NH][NN], g_gv[NH][NN];
__device__ __align__(16) float g_gqT[NN * 64];
__device__ float g_xpart[NB][64];
__device__ float g_entpart[NB];
__device__ float g_hdD[NH][NC], g_hdDg[NH][NC], g_hdSv[NH][NC];
__device__ __align__(16) float g_tkT[KMAX][NH];
__device__ __align__(16) float g_tvT[KMAX][NH];
__device__ __align__(16) float g_bkT[KMAX][NH];
__device__ __align__(16) float g_bvT[KMAX][NH];
__device__ float g_vpreT[KMAX][NH];
__device__ unsigned g_barcnt[4];      // zero-init; monotonic across replays

__constant__ float c_invf[NC] = {
    1.0f, 1.0f, 0.5f, 1.66666672e-01f, 4.16666679e-02f, 8.33333377e-03f,
    1.38888892e-03f, 1.98412701e-04f };

__device__ __forceinline__ unsigned ford(float f) {
    unsigned u = __float_as_uint(f);
    return (u & 0x80000000u) ? ~u : (u | 0x80000000u);
}

__device__ __forceinline__ float horner8(const float* c, float a) {
    float r = c[NC - 1];
#pragma unroll
    for (int j = NC - 2; j >= 0; --j) r = fmaf(r, a, c[j]);
    return r;
}

__device__ __forceinline__ void gridbar(int idx) {
    __syncthreads();
    if (threadIdx.x == 0) {
        unsigned* addr = &g_barcnt[idx];
        unsigned my;
        asm volatile("atom.release.gpu.global.add.u32 %0, [%1], 1;"
                     : "=r"(my) : "l"(addr) : "memory");
        const unsigned target = (my / (unsigned)NB + 1u) * (unsigned)NB;
        unsigned cur;
        do {
            asm volatile("ld.acquire.gpu.global.u32 %0, [%1];"
                         : "=r"(cur) : "l"(addr) : "memory");
        } while (cur < target);
    }
    __syncthreads();
}

__global__ __launch_bounds__(NT, 1)
void fused_kernel(const float* __restrict__ x,
                  const float* __restrict__ qkv_w,  const float* __restrict__ qkv_b,
                  const float* __restrict__ gqkv_w, const float* __restrict__ gqkv_b,
                  const float* __restrict__ cg_w,   const float* __restrict__ cg_b,
                  const float* __restrict__ hg_w,   const float* __restrict__ hg_b,
                  const float* __restrict__ fus_w,  const float* __restrict__ fus_b,
                  const float* __restrict__ proj_w, const float* __restrict__ proj_b,
                  float* __restrict__ out) {
    __shared__ __align__(16) float xs[RPB * 64];     // persists A->C
    __shared__ __align__(16) float xmS[RPB * 64];    // persists A->C
    __shared__ __align__(16) float qsS[RPB * 64];    // persists A->C
    __shared__ __align__(16) float kk[NN], vv[NN], gk[NN], gv[NN];
    __shared__ __align__(16) float qs[512];
    __shared__ __align__(16) float stg[4 * KMAX * 64];
    __shared__ __align__(16) float cDs[64 * NCP], cDgS[64 * NCP], cSvS[64 * NCP];
    __shared__ __align__(16) float cLp[64 * NCP], cLn[64 * NCP];
    __shared__ __align__(16) float lxS[512], gxS[512], ttS[512];
    __shared__ unsigned long long candS[160];
    __shared__ float red[25][16];
    __shared__ float Rall[25];
    __shared__ float coefD[NC], coefS1[NC];
    __shared__ float sred[64];
    __shared__ int   km_s, early_s;

    const int b = blockIdx.x;
    const int t = threadIdx.x;
    const int lane = t & 31, wid = t >> 5;
    const int n0 = b * RPB;

    // ================= Phase A: gate + qkv/gqkv GEMMs (8 rows) =================
    xs[t] = x[n0 * 64 + t];            // RPB*64 == NT
    __syncthreads();

    if (t < 64) {
        float s = 0.f;
#pragma unroll
        for (int r = 0; r < RPB; ++r) s += xs[r * 64 + t];
        g_xpart[b][t] = s;
    }
    {   // content gate (float4 LDS)
        const int c = t & 63, r = t >> 6;
        const float4* xs4 = (const float4*)xs;
        float l = cg_b[c];
#pragma unroll
        for (int j4 = 0; j4 < 16; ++j4) {
            const float w0 = cg_w[(j4 * 4 + 0) * 64 + c];
            const float w1 = cg_w[(j4 * 4 + 1) * 64 + c];
            const float w2 = cg_w[(j4 * 4 + 2) * 64 + c];
            const float w3 = cg_w[(j4 * 4 + 3) * 64 + c];
            const float4 xv = xs4[r * 16 + j4];
            l = fmaf(xv.x, w0, l); l = fmaf(xv.y, w1, l);
            l = fmaf(xv.z, w2, l); l = fmaf(xv.w, w3, l);
        }
        xmS[r * 64 + c] = (l > (float)GATE_THR) ? xs[r * 64 + c] : 0.f;
    }
    __syncthreads();

    if (t < 384) {
        const bool isg = (t >= 192);
        const int c = isg ? t - 192 : t;
        const float* wp = isg ? gqkv_w : qkv_w;
        const float4* xm4 = (const float4*)xmS;
        float acc[RPB];
        const float bias = isg ? gqkv_b[c] : qkv_b[c];
#pragma unroll
        for (int r = 0; r < RPB; ++r) acc[r] = bias;
#pragma unroll
        for (int j4 = 0; j4 < 16; ++j4) {
            const float w0 = wp[(j4 * 4 + 0) * 192 + c];
            const float w1 = wp[(j4 * 4 + 1) * 192 + c];
            const float w2 = wp[(j4 * 4 + 2) * 192 + c];
            const float w3 = wp[(j4 * 4 + 3) * 192 + c];
#pragma unroll
            for (int r = 0; r < RPB; ++r) {
                const float4 xv = xm4[r * 16 + j4];
                acc[r] = fmaf(xv.x, w0, acc[r]);
                acc[r] = fmaf(xv.y, w1, acc[r]);
                acc[r] = fmaf(xv.z, w2, acc[r]);
                acc[r] = fmaf(xv.w, w3, acc[r]);
            }
        }
        const int h = c & 63, part = c >> 6;
        if (isg && part == 0) {
            // global q: transposed store for Phase C
#pragma unroll
            for (int r = 0; r < RPB; ++r) g_gqT[(n0 + r) * 64 + h] = acc[r];
        } else {
            if (!isg && part == 0) {
#pragma unroll
                for (int r = 0; r < RPB; ++r) qsS[r * 64 + h] = acc[r];
            }
            float* dst = isg ? (part == 1 ? g_gk[h] : g_gv[h])
                             : (part == 0 ? g_q[h] : part == 1 ? g_k[h] : g_v[h]);
            *(float4*)(dst + n0)     = make_float4(acc[0], acc[1], acc[2], acc[3]);
            *(float4*)(dst + n0 + 4) = make_float4(acc[4], acc[5], acc[6], acc[7]);
        }
    }

    gridbar(0);

    // ================= Phase B: head stats (h = b>>1) =================
    const int h = b >> 1, half = b & 1;
    if (t < 256) {
        ((float4*)kk)[t] = ((const float4*)(g_k[h]))[t];
        if (half == 0) ((float4*)gk)[t] = ((const float4*)(g_gk[h]))[t];
    } else {
        ((float4*)vv)[t - 256] = ((const float4*)(g_v[h]))[t - 256];
        if (half == 0) ((float4*)gv)[t - 256] = ((const float4*)(g_gv[h]))[t - 256];
    }
    qs[t] = g_q[h][half * 512 + t];
    __syncthreads();

    if (wid < 8) {
        // ---- select: half==0 -> top-20, half==1 -> bottom-20 ----
        const bool isBot = (half == 1);
        unsigned long long key[4];
#pragma unroll
        for (int i = 0; i < 4; ++i) {
            const int m = wid * 128 + i * 32 + lane;
            unsigned f = ford(kk[m]);
            if (isBot) f = ~f;
            key[i] = ((unsigned long long)f << 32) | (unsigned)(1023 - m);
        }
        for (int it = 0; it < 20; ++it) {
            unsigned long long best = key[0]; int bi = 0;
#pragma unroll
            for (int i = 1; i < 4; ++i) if (key[i] > best) { best = key[i]; bi = i; }
            const unsigned bh = (unsigned)(best >> 32);
            const unsigned bl = (unsigned)best;
            const unsigned wbh = __reduce_max_sync(0xffffffffu, bh);
            const unsigned wbl = __reduce_max_sync(0xffffffffu, (bh == wbh) ? bl : 0u);
            if (bh == wbh && bl == wbl) key[bi] = 0ull;
            if (lane == 0) candS[wid * 20 + it] = ((unsigned long long)wbh << 32) | wbl;
        }
    } else {
        // ---- moments (256 threads x 4 elements) ----
        float M[NC + 1];
#pragma unroll
        for (int j = 0; j < NC + 1; ++j) M[j] = 0.f;
        float Mg[NC], Wg[NC];
#pragma unroll
        for (int j = 0; j < NC; ++j) { Mg[j] = 0.f; Wg[j] = 0.f; }
#pragma unroll
        for (int ii = 0; ii < 4; ++ii) {
            const int m = (t - 256) + ii * 256;
            const float kv = kk[m];
            float p = 1.f;
#pragma unroll
            for (int j = 0; j < NC + 1; ++j) { M[j] += p; p *= kv; }
            if (half == 0) {
                const float gkv = gk[m], gvv = gv[m];
                float pg = 1.f;
#pragma unroll
                for (int j = 0; j < NC; ++j) { Mg[j] += pg; Wg[j] += gvv * pg; pg *= gkv; }
            }
        }
#pragma unroll
        for (int j = 0; j < NC + 1; ++j) {
            float v = M[j];
            for (int o = 16; o; o >>= 1) v += __shfl_down_sync(0xffffffffu, v, o);
            if (lane == 0) red[j][wid - 8] = v;
        }
        if (half == 0) {
#pragma unroll
            for (int j = 0; j < NC; ++j) {
                float v = Mg[j];
                for (int o = 16; o; o >>= 1) v += __shfl_down_sync(0xffffffffu, v, o);
                if (lane == 0) red[NC + 1 + j][wid - 8] = v;
                float w = Wg[j];
                for (int o = 16; o; o >>= 1) w += __shfl_down_sync(0xffffffffu, w, o);
                if (lane == 0) red[2 * NC + 1 + j][wid - 8] = w;
            }
        }
    }
    __syncthreads();

    // warp 1: moment totals; warp 0: merge 160 candidates; t==64: vpre (half==1)
    if (wid == 1 && lane < 25) {
        float s = 0.f;
#pragma unroll
        for (int w = 0; w < 8; ++w) s += red[lane][w];
        Rall[lane] = s;
    }
    if (wid == 0) {
        unsigned long long k0 = candS[lane];
        unsigned long long k1 = candS[lane + 32];
        unsigned long long k2 = candS[lane + 64];
        unsigned long long k3 = candS[lane + 96];
        unsigned long long k4 = candS[lane + 128];
        for (int it = 0; it < 20; ++it) {
            unsigned long long best = k0; int bi = 0;
            if (k1 > best) { best = k1; bi = 1; }
            if (k2 > best) { best = k2; bi = 2; }
            if (k3 > best) { best = k3; bi = 3; }
            if (k4 > best) { best = k4; bi = 4; }
            const unsigned bh = (unsigned)(best >> 32);
            const unsigned bl = (unsigned)best;
            const unsigned wbh = __reduce_max_sync(0xffffffffu, bh);
            const unsigned wbl = __reduce_max_sync(0xffffffffu, (bh == wbh) ? bl : 0u);
            if (bh == wbh && bl == wbl) {
                if (bi == 0) k0 = 0ull; else if (bi == 1) k1 = 0ull;
                else if (bi == 2) k2 = 0ull; else if (bi == 3) k3 = 0ull; else k4 = 0ull;
            }
            if (lane == 0) {
                const int m = 1023 - (int)wbl;
                if (half == 0) { g_tkT[it][h] = kk[m]; g_tvT[it][h] = vv[m]; }
                else           { g_bkT[it][h] = kk[m]; g_bvT[it][h] = vv[m]; }
            }
        }
    }
    if (t == 64 && half == 1) {
        float s = 0.f;
        for (int i = 0; i < KMAX; ++i) { s += vv[i]; g_vpreT[i][h] = s; }
    }
    __syncthreads();

    if (t < NC) {
        const float f = c_invf[t];
        coefD[t]  = Rall[t] * f;
        coefS1[t] = Rall[t + 1] * f;
        if (half == 0) {
            g_hdD[h][t]  = coefD[t];
            g_hdDg[h][t] = Rall[NC + 1 + t] * f;
            g_hdSv[h][t] = Rall[2 * NC + 1 + t] * f;
        }
    }
    __syncthreads();

    // ---- entropy (512 rows, 1/thread) ----
    {
        const float a = qs[t] * SCALE;
        const float D = horner8(coefD, a);
        const float S1 = horner8(coefS1, a);
        float ent = __logf(D) - a * S1 / D;
        for (int o = 16; o; o >>= 1) ent += __shfl_down_sync(0xffffffffu, ent, o);
        if (lane == 0) red[0][wid] = ent;
    }
    __syncthreads();
    if (t == 0) {
        float s = 0.f;
#pragma unroll
        for (int w = 0; w < 16; ++w) s += red[0][w];
        g_entpart[b] = s;
    }

    gridbar(1);

    // ================= Phase C: km, gx, local attn, fuse, proj =================
    // km: warp 0 fixed-order (identical in every block)
    if (wid == 0) {
        float s = 0.f;
#pragma unroll
        for (int i = 0; i < 4; ++i) s += g_entpart[lane * 4 + i];
        for (int o = 16; o; o >>= 1) s += __shfl_down_sync(0xffffffffu, s, o);
        if (lane == 0) {
            const float em = s * (1.f / (float)(NH * NN));
            int km = 5 + (int)rintf(15.f * em);
            if (km < 5) km = 5;
            if (km > 20) km = 20;
            km_s = km;
        }
    }
    // staging (overlapping warp 0's reduce)
    if (t < 320) {
#pragma unroll
        for (int a4 = 0; a4 < 4; ++a4) {
            const float* src = (a4 == 0) ? &g_tkT[0][0] : (a4 == 1) ? &g_tvT[0][0]
                             : (a4 == 2) ? &g_bkT[0][0] : &g_bvT[0][0];
            ((float4*)(stg + a4 * KMAX * 64))[t] = ((const float4*)src)[t];
        }
    }
    {
        const int hh = t >> 3, j = t & 7;
        cDs[hh * NCP + j]  = (&g_hdD[0][0])[t];
        cDgS[hh * NCP + j] = (&g_hdDg[0][0])[t];
        cSvS[hh * NCP + j] = (&g_hdSv[0][0])[t];
    }
    const float gqv = g_gqT[n0 * 64 + t];
    if (t >= 384 && t < 448) {
        const int c = t - 384;
        float p = 0.f;
#pragma unroll 16
        for (int i = 0; i < NB; ++i) p += g_xpart[i][c];
        sred[c] = p * (1.f / (float)NN) * hg_w[c];
    }
    __syncthreads();
    const int km = km_s;

    if (t == 448) {
        float l = hg_b[0];
#pragma unroll
        for (int j = 0; j < 64; ++j) l += sred[j];
        const float imp = 1.f / (1.f + expf(-l));
        early_s = (imp < 0.1f) ? 1 : 0;
    }
    // gx for this block's 8 rows x 64 heads (1/thread)
    {
        const int hh = t & 63;
        const float ag = gqv * SCALE;
        gxS[t] = horner8(cSvS + hh * NCP, ag) / horner8(cDgS + hh * NCP, ag);
    }
    // local-numerator Taylor coefs per (head, sign): threads 128..255
    if (t >= 128 && t < 256) {
        const int u = t - 128;
        const int hh = u & 63;
        const bool isBot = (u >= 64);
        const float* kp = stg + (isBot ? 2 : 0) * KMAX * 64;
        const float* vp = stg + (isBot ? 3 : 1) * KMAX * 64;
        float cl[NC];
#pragma unroll
        for (int j = 0; j < NC; ++j) cl[j] = 0.f;
        for (int i = 0; i < km; ++i) {
            const float kv = kp[i * 64 + hh];
            float p = vp[i * 64 + hh];
#pragma unroll
            for (int j = 0; j < NC; ++j) { cl[j] += p; p *= kv; }
        }
        float* dst = (isBot ? cLn : cLp) + hh * NCP;
#pragma unroll
        for (int j = 0; j < NC; ++j) dst[j] = cl[j] * c_invf[j];
    }
    __syncthreads();

    // local attention (1/thread)
    {
        const int hh = t & 63, r = t >> 6;
        const float a = qsS[r * 64 + hh] * SCALE;
        const float D = horner8(cDs + hh * NCP, a);
        float num;
        if (a > 0.f)      num = horner8(cLp + hh * NCP, a);
        else if (a < 0.f) num = horner8(cLn + hh * NCP, a);
        else              num = g_vpreT[km - 1][hh];
        lxS[t] = num / D;
    }
    __syncthreads();

    const int c = t & 63, r = t >> 6;
    {
        const float4* lx4 = (const float4*)lxS;
        const float4* gx4 = (const float4*)gxS;
        float f = fus_b[c];
#pragma unroll
        for (int j4 = 0; j4 < 16; ++j4) {
            const float w0 = fus_w[(j4 * 4 + 0) * 64 + c];
            const float w1 = fus_w[(j4 * 4 + 1) * 64 + c];
            const float w2 = fus_w[(j4 * 4 + 2) * 64 + c];
            const float w3 = fus_w[(j4 * 4 + 3) * 64 + c];
            const float4 xv = lx4[r * 16 + j4];
            f = fmaf(xv.x, w0, f); f = fmaf(xv.y, w1, f);
            f = fmaf(xv.z, w2, f); f = fmaf(xv.w, w3, f);
        }
#pragma unroll
        for (int j4 = 0; j4 < 16; ++j4) {
            const float w0 = fus_w[(64 + j4 * 4 + 0) * 64 + c];
            const float w1 = fus_w[(64 + j4 * 4 + 1) * 64 + c];
            const float w2 = fus_w[(64 + j4 * 4 + 2) * 64 + c];
            const float w3 = fus_w[(64 + j4 * 4 + 3) * 64 + c];
            const float4 xv = gx4[r * 16 + j4];
            f = fmaf(xv.x, w0, f); f = fmaf(xv.y, w1, f);
            f = fmaf(xv.z, w2, f); f = fmaf(xv.w, w3, f);
        }
        ttS[r * 64 + c] = xmS[r * 64 + c] + f;
    }
    __syncthreads();
    const int early = early_s;
    {
        const float4* tt4 = (const float4*)ttS;
        float o = proj_b[c];
#pragma unroll
        for (int j4 = 0; j4 < 16; ++j4) {
            const float w0 = proj_w[(j4 * 4 + 0) * 64 + c];
            const float w1 = proj_w[(j4 * 4 + 1) * 64 + c];
            const float w2 = proj_w[(j4 * 4 + 2) * 64 + c];
            const float w3 = proj_w[(j4 * 4 + 3) * 64 + c];
            const float4 xv = tt4[r * 16 + j4];
            o = fmaf(xv.x, w0, o); o = fmaf(xv.y, w1, o);
            o = fmaf(xv.z, w2, o); o = fmaf(xv.w, w3, o);
        }
        out[(n0 + r) * 64 + c] = early ? xs[r * 64 + c] : o;
    }
}

extern "C" void kernel_launch(void* const* d_in, const int* in_sizes, int n_in,
                              void* d_out, int out_size) {
    const float* x      = (const float*)d_in[0];
    const float* qkv_w  = (const float*)d_in[1];
    const float* qkv_b  = (const float*)d_in[2];
    const float* gqkv_w = (const float*)d_in[3];
    const float* gqkv_b = (const float*)d_in[4];
    const float* cg_w   = (const float*)d_in[5];
    const float* cg_b   = (const float*)d_in[6];
    const float* hg_w   = (const float*)d_in[7];
    const float* hg_b   = (const float*)d_in[8];
    const float* fus_w  = (const float*)d_in[9];
    const float* fus_b  = (const float*)d_in[10];
    const float* proj_w = (const float*)d_in[11];
    const float* proj_b = (const float*)d_in[12];
    float* out = (float*)d_out;

    fused_kernel<<<NB, NT>>>(x, qkv_w, qkv_b, gqkv_w, gqkv_b, cg_w, cg_b,
                             hg_w, hg_b, fus_w, fus_b, proj_w, proj_b, out);
}

// round 10
// speedup vs baseline: 2.7267x; 1.0817x over previous
#include <cuda_runtime.h>
#include <math.h>

#define NN 1024
#define NH 64
#define NC 8              // Taylor terms (degree 7)
#define NCP 9             // padded stride (odd -> conflict-free)
#define SCALE 0.125f
#define KMAX 20
#define NB 128
#define NT 512
#define RPB 8
#define GATE_THR (-2.1972245773362196f)   // logit(0.1)

// -------- device scratch --------
__device__ float g_q[NH][NN], g_k[NH][NN], g_v[NH][NN];
__device__ float g_gk[NH][NN], g_gv[NH][NN];
__device__ float g_xpart[NB][64];
__device__ float g_entpart[NB];
__device__ float g_hdD[NH][NC], g_hdDg[NH][NC], g_hdSv[NH][NC];
__device__ __align__(16) float g_tkT[KMAX][NH];
__device__ __align__(16) float g_tvT[KMAX][NH];
__device__ __align__(16) float g_bkT[KMAX][NH];
__device__ __align__(16) float g_bvT[KMAX][NH];
__device__ float g_vpreT[KMAX][NH];
__device__ unsigned g_barcnt[4];      // zero-init; monotonic across replays

__constant__ float c_invf[NC] = {
    1.0f, 1.0f, 0.5f, 1.66666672e-01f, 4.16666679e-02f, 8.33333377e-03f,
    1.38888892e-03f, 1.98412701e-04f };

__device__ __forceinline__ unsigned ford(float f) {
    unsigned u = __float_as_uint(f);
    return (u & 0x80000000u) ? ~u : (u | 0x80000000u);
}

__device__ __forceinline__ float horner8(const float* c, float a) {
    float r = c[NC - 1];
#pragma unroll
    for (int j = NC - 2; j >= 0; --j) r = fmaf(r, a, c[j]);
    return r;
}

__device__ __forceinline__ void gridbar(int idx) {
    __syncthreads();
    if (threadIdx.x == 0) {
        unsigned* addr = &g_barcnt[idx];
        unsigned my;
        asm volatile("atom.release.gpu.global.add.u32 %0, [%1], 1;"
                     : "=r"(my) : "l"(addr) : "memory");
        const unsigned target = (my / (unsigned)NB + 1u) * (unsigned)NB;
        unsigned cur;
        do {
            asm volatile("ld.acquire.gpu.global.u32 %0, [%1];"
                         : "=r"(cur) : "l"(addr) : "memory");
        } while (cur < target);
    }
    __syncthreads();
}

__global__ __launch_bounds__(NT, 1)
void fused_kernel(const float* __restrict__ x,
                  const float* __restrict__ qkv_w,  const float* __restrict__ qkv_b,
                  const float* __restrict__ gqkv_w, const float* __restrict__ gqkv_b,
                  const float* __restrict__ cg_w,   const float* __restrict__ cg_b,
                  const float* __restrict__ hg_w,   const float* __restrict__ hg_b,
                  const float* __restrict__ fus_w,  const float* __restrict__ fus_b,
                  const float* __restrict__ proj_w, const float* __restrict__ proj_b,
                  float* __restrict__ out) {
    __shared__ __align__(16) float xs[512], xmS[512], qsS[512], gqS[512]; // persist A->C
    __shared__ __align__(16) float kk[NN], vv[NN];
    __shared__ __align__(16) float stg[4 * KMAX * 64];
    __shared__ __align__(16) float cDs[64 * NCP], cDgS[64 * NCP], cSvS[64 * NCP];
    __shared__ __align__(16) float cLp[64 * NCP], cLn[64 * NCP];
    __shared__ __align__(16) float lxS[512], gxS[512], ttS[512];
    __shared__ unsigned long long candS[160];
    __shared__ float red[25][16];
    __shared__ float Rall[25];
    __shared__ float coefD[NC], coefS1[NC];
    __shared__ float sred[64];
    __shared__ int   km_s, early_s;

    const int b = blockIdx.x;
    const int t = threadIdx.x;
    const int lane = t & 31, wid = t >> 5;
    const int n0 = b * RPB;

    // ================= Phase A: gate + qkv/gqkv GEMMs (8 rows) =================
    xs[t] = x[n0 * 64 + t];            // RPB*64 == NT
    __syncthreads();

    if (t < 64) {
        float s = 0.f;
#pragma unroll
        for (int r = 0; r < RPB; ++r) s += xs[r * 64 + t];
        g_xpart[b][t] = s;
    }
    if (t < 256) {   // content gate: 2 rows per thread (weight reuse)
        const int c = t & 63, rp = t >> 6;
        const int r0 = rp * 2, r1 = r0 + 1;
        const float4* xs4 = (const float4*)xs;
        float l0 = cg_b[c], l1 = l0;
#pragma unroll
        for (int j4 = 0; j4 < 16; ++j4) {
            const float w0 = cg_w[(j4 * 4 + 0) * 64 + c];
            const float w1 = cg_w[(j4 * 4 + 1) * 64 + c];
            const float w2 = cg_w[(j4 * 4 + 2) * 64 + c];
            const float w3 = cg_w[(j4 * 4 + 3) * 64 + c];
            const float4 a0 = xs4[r0 * 16 + j4];
            const float4 a1 = xs4[r1 * 16 + j4];
            l0 = fmaf(a0.x, w0, l0); l0 = fmaf(a0.y, w1, l0);
            l0 = fmaf(a0.z, w2, l0); l0 = fmaf(a0.w, w3, l0);
            l1 = fmaf(a1.x, w0, l1); l1 = fmaf(a1.y, w1, l1);
            l1 = fmaf(a1.z, w2, l1); l1 = fmaf(a1.w, w3, l1);
        }
        xmS[r0 * 64 + c] = (l0 > (float)GATE_THR) ? xs[r0 * 64 + c] : 0.f;
        xmS[r1 * 64 + c] = (l1 > (float)GATE_THR) ? xs[r1 * 64 + c] : 0.f;
    }
    __syncthreads();

    // qkv+gqkv: 192 threads, each 2 adjacent cols x 8 rows (LDS + LDG reuse)
    if (t < 192) {
        const bool isg = (t >= 96);
        const int c = (isg ? (t - 96) : t) * 2;   // even column within matrix
        const float* wp = isg ? gqkv_w : qkv_w;
        const float* bp = isg ? gqkv_b : qkv_b;
        float acc0[RPB], acc1[RPB];
        const float bias0 = bp[c], bias1 = bp[c + 1];
#pragma unroll
        for (int r = 0; r < RPB; ++r) { acc0[r] = bias0; acc1[r] = bias1; }
        const float4* xm4 = (const float4*)xmS;
#pragma unroll
        for (int j4 = 0; j4 < 16; ++j4) {
            const float2 wA = *(const float2*)(wp + (j4 * 4 + 0) * 192 + c);
            const float2 wB = *(const float2*)(wp + (j4 * 4 + 1) * 192 + c);
            const float2 wC = *(const float2*)(wp + (j4 * 4 + 2) * 192 + c);
            const float2 wD = *(const float2*)(wp + (j4 * 4 + 3) * 192 + c);
#pragma unroll
            for (int r = 0; r < RPB; ++r) {
                const float4 xv = xm4[r * 16 + j4];
                acc0[r] = fmaf(xv.x, wA.x, acc0[r]); acc1[r] = fmaf(xv.x, wA.y, acc1[r]);
                acc0[r] = fmaf(xv.y, wB.x, acc0[r]); acc1[r] = fmaf(xv.y, wB.y, acc1[r]);
                acc0[r] = fmaf(xv.z, wC.x, acc0[r]); acc1[r] = fmaf(xv.z, wC.y, acc1[r]);
                acc0[r] = fmaf(xv.w, wD.x, acc0[r]); acc1[r] = fmaf(xv.w, wD.y, acc1[r]);
            }
        }
        const int h = c & 63, part = c >> 6;   // both cols same part, heads h,h+1
        if (isg && part == 0) {
            // global q stays block-local -> smem
#pragma unroll
            for (int r = 0; r < RPB; ++r)
                *(float2*)(gqS + r * 64 + h) = make_float2(acc0[r], acc1[r]);
        } else {
            if (!isg && part == 0) {
#pragma unroll
                for (int r = 0; r < RPB; ++r)
                    *(float2*)(qsS + r * 64 + h) = make_float2(acc0[r], acc1[r]);
            }
            float* d0 = isg ? (part == 1 ? g_gk[h] : g_gv[h])
                            : (part == 0 ? g_q[h] : part == 1 ? g_k[h] : g_v[h]);
            float* d1 = isg ? (part == 1 ? g_gk[h + 1] : g_gv[h + 1])
                            : (part == 0 ? g_q[h + 1] : part == 1 ? g_k[h + 1] : g_v[h + 1]);
            *(float4*)(d0 + n0)     = make_float4(acc0[0], acc0[1], acc0[2], acc0[3]);
            *(float4*)(d0 + n0 + 4) = make_float4(acc0[4], acc0[5], acc0[6], acc0[7]);
            *(float4*)(d1 + n0)     = make_float4(acc1[0], acc1[1], acc1[2], acc1[3]);
            *(float4*)(d1 + n0 + 4) = make_float4(acc1[4], acc1[5], acc1[6], acc1[7]);
        }
    }

    gridbar(0);

    // ================= Phase B: head stats (h = b>>1) =================
    const int h = b >> 1, half = b & 1;
    if (t < 256) ((float4*)kk)[t] = ((const float4*)(g_k[h]))[t];
    else         ((float4*)vv)[t - 256] = ((const float4*)(g_v[h]))[t - 256];
    const float qreg = g_q[h][half * 512 + t];
    __syncthreads();

    if (wid < 8) {
        // ---- select: half==0 -> top-20, half==1 -> bottom-20 ----
        const bool isBot = (half == 1);
        unsigned long long key[4];
#pragma unroll
        for (int i = 0; i < 4; ++i) {
            const int m = wid * 128 + i * 32 + lane;
            unsigned f = ford(kk[m]);
            if (isBot) f = ~f;
            key[i] = ((unsigned long long)f << 32) | (unsigned)(1023 - m);
        }
        for (int it = 0; it < 20; ++it) {
            unsigned long long best = key[0]; int bi = 0;
#pragma unroll
            for (int i = 1; i < 4; ++i) if (key[i] > best) { best = key[i]; bi = i; }
            const unsigned bh = (unsigned)(best >> 32);
            const unsigned bl = (unsigned)best;
            const unsigned wbh = __reduce_max_sync(0xffffffffu, bh);
            const unsigned wbl = __reduce_max_sync(0xffffffffu, (bh == wbh) ? bl : 0u);
            if (bh == wbh && bl == wbl) key[bi] = 0ull;
            if (lane == 0) candS[wid * 20 + it] = ((unsigned long long)wbh << 32) | wbl;
        }
    } else {
        // ---- moments: 256 threads x 4 elements (float4, gk/gv streamed) ----
        const int u = t - 256;
        float M[NC + 1];
#pragma unroll
        for (int j = 0; j < NC + 1; ++j) M[j] = 0.f;
        float Mg[NC], Wg[NC];
#pragma unroll
        for (int j = 0; j < NC; ++j) { Mg[j] = 0.f; Wg[j] = 0.f; }
        {
            const float4 k4 = ((const float4*)kk)[u];
            const float e[4] = {k4.x, k4.y, k4.z, k4.w};
#pragma unroll
            for (int q4 = 0; q4 < 4; ++q4) {
                float p = 1.f;
#pragma unroll
                for (int j = 0; j < NC + 1; ++j) { M[j] += p; p *= e[q4]; }
            }
        }
        if (half == 0) {
            const float4 gk4 = ((const float4*)(g_gk[h]))[u];
            const float4 gv4 = ((const float4*)(g_gv[h]))[u];
            const float ek[4] = {gk4.x, gk4.y, gk4.z, gk4.w};
            const float ev[4] = {gv4.x, gv4.y, gv4.z, gv4.w};
#pragma unroll
            for (int q4 = 0; q4 < 4; ++q4) {
                float p = 1.f;
#pragma unroll
                for (int j = 0; j < NC; ++j) { Mg[j] += p; Wg[j] += ev[q4] * p; p *= ek[q4]; }
            }
        }
#pragma unroll
        for (int j = 0; j < NC + 1; ++j) {
            float v = M[j];
            for (int o = 16; o; o >>= 1) v += __shfl_down_sync(0xffffffffu, v, o);
            if (lane == 0) red[j][wid - 8] = v;
        }
        if (half == 0) {
#pragma unroll
            for (int j = 0; j < NC; ++j) {
                float v = Mg[j];
                for (int o = 16; o; o >>= 1) v += __shfl_down_sync(0xffffffffu, v, o);
                if (lane == 0) red[NC + 1 + j][wid - 8] = v;
                float w = Wg[j];
                for (int o = 16; o; o >>= 1) w += __shfl_down_sync(0xffffffffu, w, o);
                if (lane == 0) red[2 * NC + 1 + j][wid - 8] = w;
            }
        }
    }
    __syncthreads();

    // warp 1: moment totals; warp 0: merge 160 candidates; t==64: vpre (half==1)
    if (wid == 1 && lane < 25) {
        float s = 0.f;
#pragma unroll
        for (int w = 0; w < 8; ++w) s += red[lane][w];
        Rall[lane] = s;
    }
    if (wid == 0) {
        unsigned long long k0 = candS[lane];
        unsigned long long k1 = candS[lane + 32];
        unsigned long long k2 = candS[lane + 64];
        unsigned long long k3 = candS[lane + 96];
        unsigned long long k4 = candS[lane + 128];
        for (int it = 0; it < 20; ++it) {
            unsigned long long best = k0; int bi = 0;
            if (k1 > best) { best = k1; bi = 1; }
            if (k2 > best) { best = k2; bi = 2; }
            if (k3 > best) { best = k3; bi = 3; }
            if (k4 > best) { best = k4; bi = 4; }
            const unsigned bh = (unsigned)(best >> 32);
            const unsigned bl = (unsigned)best;
            const unsigned wbh = __reduce_max_sync(0xffffffffu, bh);
            const unsigned wbl = __reduce_max_sync(0xffffffffu, (bh == wbh) ? bl : 0u);
            if (bh == wbh && bl == wbl) {
                if (bi == 0) k0 = 0ull; else if (bi == 1) k1 = 0ull;
                else if (bi == 2) k2 = 0ull; else if (bi == 3) k3 = 0ull; else k4 = 0ull;
            }
            if (lane == 0) {
                const int m = 1023 - (int)wbl;
                if (half == 0) { g_tkT[it][h] = kk[m]; g_tvT[it][h] = vv[m]; }
                else           { g_bkT[it][h] = kk[m]; g_bvT[it][h] = vv[m]; }
            }
        }
    }
    if (t == 64 && half == 1) {
        float s = 0.f;
        for (int i = 0; i < KMAX; ++i) { s += vv[i]; g_vpreT[i][h] = s; }
    }
    __syncthreads();

    if (t < NC) {
        const float f = c_invf[t];
        coefD[t]  = Rall[t] * f;
        coefS1[t] = Rall[t + 1] * f;
        if (half == 0) {
            g_hdD[h][t]  = coefD[t];
            g_hdDg[h][t] = Rall[NC + 1 + t] * f;
            g_hdSv[h][t] = Rall[2 * NC + 1 + t] * f;
        }
    }
    __syncthreads();

    // ---- entropy (512 rows, 1/thread) ----
    {
        const float a = qreg * SCALE;
        const float D = horner8(coefD, a);
        const float S1 = horner8(coefS1, a);
        float ent = __logf(D) - a * S1 / D;
        for (int o = 16; o; o >>= 1) ent += __shfl_down_sync(0xffffffffu, ent, o);
        if (lane == 0) red[0][wid] = ent;
    }
    __syncthreads();
    if (t == 0) {
        float s = 0.f;
#pragma unroll
        for (int w = 0; w < 16; ++w) s += red[0][w];
        g_entpart[b] = s;
    }

    gridbar(1);

    // ================= Phase C: km, gx, local attn, fuse, proj =================
    if (wid == 0) {   // km: fixed-order, identical in every block
        float s = 0.f;
#pragma unroll
        for (int i = 0; i < 4; ++i) s += g_entpart[lane * 4 + i];
        for (int o = 16; o; o >>= 1) s += __shfl_down_sync(0xffffffffu, s, o);
        if (lane == 0) {
            const float em = s * (1.f / (float)(NH * NN));
            int km = 5 + (int)rintf(15.f * em);
            if (km < 5) km = 5;
            if (km > 20) km = 20;
            km_s = km;
        }
    }
    if (t < 320) {
#pragma unroll
        for (int a4 = 0; a4 < 4; ++a4) {
            const float* src = (a4 == 0) ? &g_tkT[0][0] : (a4 == 1) ? &g_tvT[0][0]
                             : (a4 == 2) ? &g_bkT[0][0] : &g_bvT[0][0];
            ((float4*)(stg + a4 * KMAX * 64))[t] = ((const float4*)src)[t];
        }
    }
    {
        const int hh = t >> 3, j = t & 7;
        cDs[hh * NCP + j]  = (&g_hdD[0][0])[t];
        cDgS[hh * NCP + j] = (&g_hdDg[0][0])[t];
        cSvS[hh * NCP + j] = (&g_hdSv[0][0])[t];
    }
    if (t >= 384 && t < 448) {
        const int c = t - 384;
        float p = 0.f;
#pragma unroll 16
        for (int i = 0; i < NB; ++i) p += g_xpart[i][c];
        sred[c] = p * (1.f / (float)NN) * hg_w[c];
    }
    __syncthreads();
    const int km = km_s;

    if (t == 448) {
        float l = hg_b[0];
#pragma unroll
        for (int j = 0; j < 64; ++j) l += sred[j];
        const float imp = 1.f / (1.f + expf(-l));
        early_s = (imp < 0.1f) ? 1 : 0;
    }
    {   // gx (1/thread), from block-local gqS
        const int hh = t & 63;
        const float ag = gqS[t] * SCALE;
        gxS[t] = horner8(cSvS + hh * NCP, ag) / horner8(cDgS + hh * NCP, ag);
    }
    if (t >= 128 && t < 256) {   // local-numerator Taylor coefs per (head, sign)
        const int u = t - 128;
        const int hh = u & 63;
        const bool isBot = (u >= 64);
        const float* kp = stg + (isBot ? 2 : 0) * KMAX * 64;
        const float* vp = stg + (isBot ? 3 : 1) * KMAX * 64;
        float cl[NC];
#pragma unroll
        for (int j = 0; j < NC; ++j) cl[j] = 0.f;
        for (int i = 0; i < km; ++i) {
            const float kv = kp[i * 64 + hh];
            float p = vp[i * 64 + hh];
#pragma unroll
            for (int j = 0; j < NC; ++j) { cl[j] += p; p *= kv; }
        }
        float* dst = (isBot ? cLn : cLp) + hh * NCP;
#pragma unroll
        for (int j = 0; j < NC; ++j) dst[j] = cl[j] * c_invf[j];
    }
    __syncthreads();

    // local attention (1/thread)
    {
        const int hh = t & 63;
        const float a = qsS[t] * SCALE;
        const float D = horner8(cDs + hh * NCP, a);
        float num;
        if (a > 0.f)      num = horner8(cLp + hh * NCP, a);
        else if (a < 0.f) num = horner8(cLn + hh * NCP, a);
        else              num = g_vpreT[km - 1][hh];
        lxS[t] = num / D;
    }
    __syncthreads();

    // fuse: 256 threads x 2 rows (weight reuse)
    if (t < 256) {
        const int c = t & 63, rp = t >> 6;
        const int r0 = rp * 2, r1 = r0 + 1;
        const float4* lx4 = (const float4*)lxS;
        const float4* gx4 = (const float4*)gxS;
        float f0 = fus_b[c], f1 = f0;
#pragma unroll
        for (int j4 = 0; j4 < 16; ++j4) {
            const float w0 = fus_w[(j4 * 4 + 0) * 64 + c];
            const float w1 = fus_w[(j4 * 4 + 1) * 64 + c];
            const float w2 = fus_w[(j4 * 4 + 2) * 64 + c];
            const float w3 = fus_w[(j4 * 4 + 3) * 64 + c];
            const float4 a0 = lx4[r0 * 16 + j4];
            const float4 a1 = lx4[r1 * 16 + j4];
            f0 = fmaf(a0.x, w0, f0); f0 = fmaf(a0.y, w1, f0);
            f0 = fmaf(a0.z, w2, f0); f0 = fmaf(a0.w, w3, f0);
            f1 = fmaf(a1.x, w0, f1); f1 = fmaf(a1.y, w1, f1);
            f1 = fmaf(a1.z, w2, f1); f1 = fmaf(a1.w, w3, f1);
        }
#pragma unroll
        for (int j4 = 0; j4 < 16; ++j4) {
            const float w0 = fus_w[(64 + j4 * 4 + 0) * 64 + c];
            const float w1 = fus_w[(64 + j4 * 4 + 1) * 64 + c];
            const float w2 = fus_w[(64 + j4 * 4 + 2) * 64 + c];
            const float w3 = fus_w[(64 + j4 * 4 + 3) * 64 + c];
            const float4 a0 = gx4[r0 * 16 + j4];
            const float4 a1 = gx4[r1 * 16 + j4];
            f0 = fmaf(a0.x, w0, f0); f0 = fmaf(a0.y, w1, f0);
            f0 = fmaf(a0.z, w2, f0); f0 = fmaf(a0.w, w3, f0);
            f1 = fmaf(a1.x, w0, f1); f1 = fmaf(a1.y, w1, f1);
            f1 = fmaf(a1.z, w2, f1); f1 = fmaf(a1.w, w3, f1);
        }
        ttS[r0 * 64 + c] = xmS[r0 * 64 + c] + f0;
        ttS[r1 * 64 + c] = xmS[r1 * 64 + c] + f1;
    }
    __syncthreads();
    const int early = early_s;
    if (t < 256) {   // proj: 2 rows per thread
        const int c = t & 63, rp = t >> 6;
        const int r0 = rp * 2, r1 = r0 + 1;
        const float4* tt4 = (const float4*)ttS;
        float o0 = proj_b[c], o1 = o0;
#pragma unroll
        for (int j4 = 0; j4 < 16; ++j4) {
            const float w0 = proj_w[(j4 * 4 + 0) * 64 + c];
            const float w1 = proj_w[(j4 * 4 + 1) * 64 + c];
            const float w2 = proj_w[(j4 * 4 + 2) * 64 + c];
            const float w3 = proj_w[(j4 * 4 + 3) * 64 + c];
            const float4 a0 = tt4[r0 * 16 + j4];
            const float4 a1 = tt4[r1 * 16 + j4];
            o0 = fmaf(a0.x, w0, o0); o0 = fmaf(a0.y, w1, o0);
            o0 = fmaf(a0.z, w2, o0); o0 = fmaf(a0.w, w3, o0);
            o1 = fmaf(a1.x, w0, o1); o1 = fmaf(a1.y, w1, o1);
            o1 = fmaf(a1.z, w2, o1); o1 = fmaf(a1.w, w3, o1);
        }
        out[(n0 + r0) * 64 + c] = early ? xs[r0 * 64 + c] : o0;
        out[(n0 + r1) * 64 + c] = early ? xs[r1 * 64 + c] : o1;
    }
}

extern "C" void kernel_launch(void* const* d_in, const int* in_sizes, int n_in,
                              void* d_out, int out_size) {
    const float* x      = (const float*)d_in[0];
    const float* qkv_w  = (const float*)d_in[1];
    const float* qkv_b  = (const float*)d_in[2];
    const float* gqkv_w = (const float*)d_in[3];
    const float* gqkv_b = (const float*)d_in[4];
    const float* cg_w   = (const float*)d_in[5];
    const float* cg_b   = (const float*)d_in[6];
    const float* hg_w   = (const float*)d_in[7];
    const float* hg_b   = (const float*)d_in[8];
    const float* fus_w  = (const float*)d_in[9];
    const float* fus_b  = (const float*)d_in[10];
    const float* proj_w = (const float*)d_in[11];
    const float* proj_b = (const float*)d_in[12];
    float* out = (float*)d_out;

    fused_kernel<<<NB, NT>>>(x, qkv_w, qkv_b, gqkv_w, gqkv_b, cg_w, cg_b,
                             hg_w, hg_b, fus_w, fus_b, proj_w, proj_b, out);
}